// round 11
// baseline (speedup 1.0000x reference)
#include <cuda_runtime.h>
#include <cuda_bf16.h>
#include <math.h>
#include <stdint.h>

#define TT 64
#define BB 2048
#define OBS 48
#define HH 256
#define G4 1024
#define KC 304
#define M1 512
#define M2 256
#define TB (TT*BB)
#define LOG2PI 1.8378770664093453f

typedef __nv_bfloat16 bf16;

// ---------------- scratch ----------------
__device__ __align__(16) bf16 g_Wc[G4 * KC];
__device__ float            g_bias[G4];
__device__ __align__(16) bf16 g_W1b[M1 * HH];
__device__ __align__(16) bf16 g_W2b[M2 * M1];
__device__ __align__(16) bf16 g_xb[(size_t)TB * OBS];
__device__ __align__(16) bf16 g_hb[(size_t)TB * HH];

// ---------------- helpers ----------------
__device__ __forceinline__ uint32_t bf2_as_u32(__nv_bfloat162 v) {
    return *reinterpret_cast<uint32_t*>(&v);
}

__device__ __forceinline__ void mma16816(float c[4],
    uint32_t a0, uint32_t a1, uint32_t a2, uint32_t a3,
    uint32_t b0, uint32_t b1)
{
    asm volatile(
        "mma.sync.aligned.m16n8k16.row.col.f32.bf16.bf16.f32 "
        "{%0,%1,%2,%3}, {%4,%5,%6,%7}, {%8,%9}, {%0,%1,%2,%3};"
        : "+f"(c[0]), "+f"(c[1]), "+f"(c[2]), "+f"(c[3])
        : "r"(a0), "r"(a1), "r"(a2), "r"(a3), "r"(b0), "r"(b1));
}

__device__ __forceinline__ void ldsm4(uint32_t& r0, uint32_t& r1,
                                      uint32_t& r2, uint32_t& r3, uint32_t addr)
{
    asm volatile("ldmatrix.sync.aligned.m8n8.x4.shared.b16 {%0,%1,%2,%3}, [%4];"
                 : "=r"(r0), "=r"(r1), "=r"(r2), "=r"(r3) : "r"(addr));
}

__device__ __forceinline__ uint32_t smem_u32(const void* p) {
    uint32_t a;
    asm("{ .reg .u64 t; cvta.to.shared.u64 t, %1; cvt.u32.u64 %0, t; }"
        : "=r"(a) : "l"(p));
    return a;
}

__device__ __forceinline__ float tanha(float x) {
    float r; asm("tanh.approx.f32 %0, %1;" : "=f"(r) : "f"(x)); return r;
}
__device__ __forceinline__ float sigm(float x) {
    return fmaf(0.5f, tanha(0.5f * x), 0.5f);
}

// ---------------- prep kernels ----------------
__global__ void prep_wc(const float* __restrict__ W_hh, const float* __restrict__ W_ih,
                        const float* __restrict__ b_ih, const float* __restrict__ b_hh)
{
    int idx = blockIdx.x * blockDim.x + threadIdx.x;
    if (idx >= G4 * KC) return;
    int n = idx / KC, k = idx % KC;
    int g = n & 3, j = n >> 2;
    float v = (k < HH) ? W_hh[(size_t)(g * HH + j) * HH + k]
                       : W_ih[(size_t)(g * HH + j) * OBS + (k - HH)];
    g_Wc[idx] = __float2bfloat16(v);
    if (k == 0) g_bias[n] = b_ih[g * HH + j] + b_hh[g * HH + j];
}

__global__ void prep_w12(const float* __restrict__ W1, const float* __restrict__ W2)
{
    int idx = blockIdx.x * blockDim.x + threadIdx.x;
    if (idx >= M1 * HH + M2 * M1) return;
    if (idx < M1 * HH) {
        int n = idx / HH, k = idx % HH;
        g_W1b[idx] = __float2bfloat16(W1[(size_t)k * M1 + n]);
    } else {
        int i = idx - M1 * HH;
        int n = i / M1, k = i % M1;
        g_W2b[i] = __float2bfloat16(W2[(size_t)k * M2 + n]);
    }
}

__global__ void prep_x(const float* __restrict__ x)
{
    size_t idx = (size_t)blockIdx.x * blockDim.x + threadIdx.x;
    if (idx < (size_t)TB * OBS) g_xb[idx] = __float2bfloat16(x[idx]);
}

// ---------------- persistent cluster LSTM (512 threads, 16 warps) ----------------
#define SM_BIAS  0
#define SM_A     1024
#define SM_STAGE 43008
#define SM_B     52224
#define SM_TOTAL 220160
#define ASTR_B 656
#define STG_B  144

__global__ void __launch_bounds__(512, 1) __cluster_dims__(4, 1, 1)
lstm_persist(const float* __restrict__ h0, const float* __restrict__ c0,
             const int* __restrict__ done)
{
    extern __shared__ char smx[];
    const uint32_t smb = smem_u32(smx);

    const int tid = threadIdx.x;
    const int lane = tid & 31, warp = tid >> 5;
    const int wm = warp & 1, wn = warp >> 1;      // 2 x 8 warp grid (m x n)
    const int g8 = lane >> 2, t4 = lane & 3;

    uint32_t rank;
    asm("mov.u32 %0, %%cluster_ctarank;" : "=r"(rank));
    const int b0 = (blockIdx.x >> 2) * 64;
    const int jbase = rank * 64;

    float* bias_s = (float*)(smx + SM_BIAS);
    if (tid < 256) bias_s[tid] = g_bias[rank * 256 + tid];

    for (int u = tid; u < 256 * 38; u += 512) {
        int n = u / 38, off = u % 38;
        uint4 v = *(const uint4*)((const char*)g_Wc + (size_t)(rank * 256 + n) * 608 + off * 16);
        *(uint4*)(smx + SM_B + n * ASTR_B + off * 16) = v;
    }
    for (int u = tid; u < 4096; u += 512) {      // h0 -> bf16
        int row = u >> 6, c4 = u & 63;
        float4 v = *(const float4*)(h0 + (size_t)(b0 + row) * HH + c4 * 4);
        uint2 p;
        p.x = bf2_as_u32(__floats2bfloat162_rn(v.x, v.y));
        p.y = bf2_as_u32(__floats2bfloat162_rn(v.z, v.w));
        *(uint2*)(smx + SM_A + row * ASTR_B + c4 * 8) = p;
    }
    if (tid < 384) {   // x(t=0)
        const uint4* xs = (const uint4*)(g_xb + (size_t)b0 * OBS);
        uint4 v = xs[tid];
        int e = tid * 8, row = e / 48, col = e % 48;
        *(uint4*)(smx + SM_A + row * ASTR_B + 512 + col * 2) = v;
    }
    // c in registers: 8 cells per thread
    float creg[8];
#pragma unroll
    for (int am = 0; am < 2; am++)
#pragma unroll
        for (int an = 0; an < 4; an++) {
            int r = wm * 32 + am * 16 + g8 + (t4 & 1) * 8;
            int jl = wn * 8 + an * 2 + (t4 >> 1);
            creg[am * 4 + an] = c0[(size_t)(b0 + r) * HH + jbase + jl];
        }
    __syncthreads();

    const int mi = lane >> 3;
    const int rowoff = ((mi & 1) << 3) + (lane & 7);
    const uint32_t kboff = (uint32_t)((mi >> 1) << 4);
    uint32_t aBase[2], bBase[2];
#pragma unroll
    for (int am = 0; am < 2; am++)
        aBase[am] = smb + SM_A + (wm * 32 + am * 16 + rowoff) * ASTR_B + kboff;
#pragma unroll
    for (int p = 0; p < 2; p++)
        bBase[p] = smb + SM_B + (wn * 32 + p * 16 + rowoff) * ASTR_B + kboff;

    uint32_t peerA[4];
#pragma unroll
    for (int r = 0; r < 4; r++) {
        uint32_t a;
        asm("mapa.shared::cluster.u32 %0, %1, %2;" : "=r"(a) : "r"(smb + SM_A), "r"(r));
        peerA[r] = a;
    }

    const int base_r = wm * 32 + g8;
    int d0, d1, d2, d3;
    {
        const int* dt = done + b0;
        d0 = dt[base_r]; d1 = dt[base_r + 8];
        d2 = dt[base_r + 16]; d3 = dt[base_r + 24];
    }

#pragma unroll 1
    for (int t = 0; t < TT; t++) {
        uint32_t m0 = d0 ? 0u : ~0u, m1 = d1 ? 0u : ~0u;
        uint32_t m2 = d2 ? 0u : ~0u, m3 = d3 ? 0u : ~0u;

        float acc[2][4][4];
#pragma unroll
        for (int i = 0; i < 2; i++)
#pragma unroll
            for (int j = 0; j < 4; j++)
#pragma unroll
                for (int k = 0; k < 4; k++) acc[i][j][k] = 0.0f;

        if (t)
            asm volatile("barrier.cluster.wait.aligned;" ::: "memory");

#pragma unroll
        for (int ch = 0; ch < 19; ch++) {
            uint32_t a[2][4];
            ldsm4(a[0][0], a[0][1], a[0][2], a[0][3], aBase[0] + ch * 32);
            ldsm4(a[1][0], a[1][1], a[1][2], a[1][3], aBase[1] + ch * 32);
            if (ch < 16) {
                a[0][0] &= m0; a[0][2] &= m0; a[0][1] &= m1; a[0][3] &= m1;
                a[1][0] &= m2; a[1][2] &= m2; a[1][1] &= m3; a[1][3] &= m3;
            }
#pragma unroll
            for (int p = 0; p < 2; p++) {
                uint32_t br0, br1, br2, br3;
                ldsm4(br0, br1, br2, br3, bBase[p] + ch * 32);
#pragma unroll
                for (int am = 0; am < 2; am++) {
                    mma16816(acc[am][2 * p],     a[am][0], a[am][1], a[am][2], a[am][3], br0, br2);
                    mma16816(acc[am][2 * p + 1], a[am][0], a[am][1], a[am][2], a[am][3], br1, br3);
                }
            }
        }

        asm volatile("barrier.cluster.arrive.aligned;" ::: "memory");   // B1 arrive

        uint4 xr0;
        int dn0 = 0, dn1 = 0, dn2 = 0, dn3 = 0;
        const bool hx = (t < TT - 1);
        if (hx) {
            if (tid < 384) {
                const uint4* xs = (const uint4*)(g_xb + ((size_t)(t + 1) * BB + b0) * OBS);
                xr0 = xs[tid];
            }
            const int* dt = done + (size_t)(t + 1) * BB + b0;
            dn0 = dt[base_r]; dn1 = dt[base_r + 8];
            dn2 = dt[base_r + 16]; dn3 = dt[base_r + 24];
        }

        const bool odd = (t4 & 1);
#pragma unroll
        for (int am = 0; am < 2; am++) {
            const int dlo = (am == 0) ? d0 : d2;
            const int dhi = (am == 0) ? d1 : d3;
            const int dflag = odd ? dhi : dlo;
#pragma unroll
            for (int an = 0; an < 4; an++) {
                float* a = acc[am][an];
                float s0 = odd ? a[0] : a[2];
                float s1 = odd ? a[1] : a[3];
                float e0 = __shfl_xor_sync(0xffffffffu, s0, 1);
                float e1 = __shfl_xor_sync(0xffffffffu, s1, 1);
                float q0 = odd ? e0 : a[0];
                float q1 = odd ? e1 : a[1];
                float q2 = odd ? a[2] : e0;
                float q3 = odd ? a[3] : e1;
                int jl = wn * 8 + an * 2 + (t4 >> 1);
                float4 bb = *(const float4*)&bias_s[jl * 4];
                float gi = q0 + bb.x, gf = q1 + bb.y, gg = q2 + bb.z, go = q3 + bb.w;
                int cell = am * 4 + an;
                float cold = dflag ? 0.0f : creg[cell];
                float cn = sigm(gf) * cold + sigm(gi) * tanha(gg);
                creg[cell] = cn;
                float hn = sigm(go) * tanha(cn);
                int r = wm * 32 + am * 16 + g8 + (odd ? 8 : 0);
                *(bf16*)(smx + SM_STAGE + r * STG_B + jl * 2) = __float2bfloat16(hn);
            }
        }

        if (hx && tid < 384) {
            int e = tid * 8;
            *(uint4*)(smx + SM_A + (e / 48) * ASTR_B + 512 + (e % 48) * 2) = xr0;
        }

        __syncthreads();
        asm volatile("barrier.cluster.wait.aligned;" ::: "memory");     // B1 wait

        {
            int row = tid >> 3, off = tid & 7;
            uint4 v = *(const uint4*)(smx + SM_STAGE + row * STG_B + off * 16);
#pragma unroll
            for (int r = 0; r < 4; r++) {
                uint32_t da = peerA[r] + row * ASTR_B + jbase * 2 + off * 16;
                asm volatile("st.shared::cluster.v4.b32 [%0], {%1,%2,%3,%4};"
                             :: "r"(da), "r"(v.x), "r"(v.y), "r"(v.z), "r"(v.w) : "memory");
            }
            *(uint4*)(g_hb + ((size_t)t * BB + b0 + row) * HH + jbase + off * 8) = v;
        }

        asm volatile("barrier.cluster.arrive.aligned;" ::: "memory");   // B2 arrive
        d0 = dn0; d1 = dn1; d2 = dn2; d3 = dn3;
    }
    asm volatile("barrier.cluster.wait.aligned;" ::: "memory");
}

// ---------------- fused LN + MLP1 + MLP2 + heads ----------------
// 512 threads, 64 rows per block. LN on A-load, y1 tile in smem,
// W1/W2 streamed, heads block-local.
// smem (bytes):
#define F_A    0            // 64 x 528  = 33792   (LN(h), bf16, stride 264 el)
#define F_Y    33792        // 64 x 1040 = 66560   (y1 bf16, stride 520 el)
#define F_B    100352       // B stream buf, 256 x 80 = 20480
#define F_WC   120832       // heads weights 24 x 260 f32 = 24960
#define F_GB   145792       // gamma|beta 512 f32 = 2048
#define F_TOTAL 147840

__global__ void __launch_bounds__(512) mlp_fused(
    const bf16* __restrict__ Ain, const bf16* __restrict__ W1b,
    const float* __restrict__ b1, const bf16* __restrict__ W2b,
    const float* __restrict__ b2,
    const float* __restrict__ ln_g, const float* __restrict__ ln_b,
    const float* __restrict__ Wm, const float* __restrict__ bm,
    const float* __restrict__ Ws, const float* __restrict__ bsv,
    float* __restrict__ outF)
{
    extern __shared__ char sm[];
    const int tid = threadIdx.x;
    const int lane = tid & 31, warp = tid >> 5;
    const int wm = warp & 1, wn = warp >> 1;      // 2 x 8 warp grid
    const int g8 = lane >> 2, t4 = lane & 3;
    const size_t m0 = (size_t)blockIdx.x * 64;

    float* gb = (float*)(sm + F_GB);
    float* wc = (float*)(sm + F_WC);

    gb[tid] = (tid < 256) ? __ldg(&ln_g[tid]) : __ldg(&ln_b[tid - 256]);
    for (int u = tid; u < 24 * 256; u += 512) {
        int o = u % 24, k = u / 24;
        wc[o * 260 + k] = (o < 12) ? __ldg(&Wm[k * 12 + o]) : __ldg(&Ws[k * 12 + (o - 12)]);
    }
    __syncthreads();

    // ---- LN(h) -> smA (8 threads per row, 32 cols each) ----
    {
        int row = tid >> 3, seg = tid & 7;
        uint4 hv[4];
#pragma unroll
        for (int i = 0; i < 4; i++)
            hv[i] = *(const uint4*)(Ain + (m0 + row) * HH + seg * 32 + i * 8);
        float s = 0.0f, s2 = 0.0f;
#pragma unroll
        for (int i = 0; i < 4; i++) {
            const __nv_bfloat162* p = (const __nv_bfloat162*)&hv[i];
#pragma unroll
            for (int q = 0; q < 4; q++) {
                float2 f = __bfloat1622float2(p[q]);
                s += f.x + f.y;
                s2 += f.x * f.x + f.y * f.y;
            }
        }
#pragma unroll
        for (int o = 1; o < 8; o <<= 1) {
            s  += __shfl_xor_sync(0xffffffffu, s, o);
            s2 += __shfl_xor_sync(0xffffffffu, s2, o);
        }
        float mu = s * (1.0f / HH);
        float rs = rsqrtf(s2 * (1.0f / HH) - mu * mu + 1e-5f);
#pragma unroll
        for (int i = 0; i < 4; i++) {
            __nv_bfloat162* p = (__nv_bfloat162*)&hv[i];
            int cb = seg * 32 + i * 8;
#pragma unroll
            for (int q = 0; q < 4; q++) {
                float2 f = __bfloat1622float2(p[q]);
                int c = cb + 2 * q;
                f.x = (f.x - mu) * rs * gb[c]     + gb[256 + c];
                f.y = (f.y - mu) * rs * gb[c + 1] + gb[256 + c + 1];
                p[q] = __floats2bfloat162_rn(f.x, f.y);
            }
            *(uint4*)(sm + F_A + row * 528 + seg * 64 + i * 16) = hv[i];
        }
    }
    __syncthreads();

    const int mi = lane >> 3;
    const int rowoff = ((mi & 1) << 3) + (lane & 7);
    const uint32_t kb16 = (uint32_t)((mi >> 1) << 4);
    const uint32_t smAu = smem_u32(sm + F_A);
    const uint32_t smYu = smem_u32(sm + F_Y);
    const uint32_t smBu = smem_u32(sm + F_B);

    uint32_t aB1[2], aB2[2];
#pragma unroll
    for (int am = 0; am < 2; am++) {
        aB1[am] = smAu + (wm * 32 + am * 16 + rowoff) * 528 + kb16;
        aB2[am] = smYu + (wm * 32 + am * 16 + rowoff) * 1040 + kb16;
    }
    const uint32_t bB1 = smBu + (wn * 16 + rowoff) * 80 + kb16;
    uint32_t bB2[2];
#pragma unroll
    for (int p = 0; p < 2; p++)
        bB2[p] = smBu + (wn * 32 + p * 16 + rowoff) * 80 + kb16;

    // ---- stage 1: y1 = ELU(A @ W1^T + b1), 4 passes of N=128 ----
#pragma unroll 1
    for (int pass = 0; pass < 4; pass++) {
        const int n0 = pass * 128;
        // prefetch chunk 0: 128 rows x 32k, 1 uint4/thread
        int brow = tid >> 2, bq = tid & 3;
        uint4 breg = *(const uint4*)(W1b + (size_t)(n0 + brow) * HH + bq * 8);

        float acc[2][2][4];
#pragma unroll
        for (int i = 0; i < 2; i++)
#pragma unroll
            for (int j = 0; j < 2; j++)
#pragma unroll
                for (int k = 0; k < 4; k++) acc[i][j][k] = 0.0f;

#pragma unroll 1
        for (int c = 0; c < 8; c++) {
            __syncthreads();
            *(uint4*)(sm + F_B + brow * 80 + bq * 16) = breg;
            __syncthreads();
            if (c + 1 < 8)
                breg = *(const uint4*)(W1b + (size_t)(n0 + brow) * HH + (c + 1) * 32 + bq * 8);
#pragma unroll
            for (int ks = 0; ks < 2; ks++) {
                int s = c * 2 + ks;
                uint32_t a[2][4];
                ldsm4(a[0][0], a[0][1], a[0][2], a[0][3], aB1[0] + s * 32);
                ldsm4(a[1][0], a[1][1], a[1][2], a[1][3], aB1[1] + s * 32);
                uint32_t br0, br1, br2, br3;
                ldsm4(br0, br1, br2, br3, bB1 + ks * 32);
#pragma unroll
                for (int am = 0; am < 2; am++) {
                    mma16816(acc[am][0], a[am][0], a[am][1], a[am][2], a[am][3], br0, br2);
                    mma16816(acc[am][1], a[am][0], a[am][1], a[am][2], a[am][3], br1, br3);
                }
            }
        }
        // epilogue -> smY (bf16)
#pragma unroll
        for (int am = 0; am < 2; am++)
#pragma unroll
            for (int an = 0; an < 2; an++) {
                int r = wm * 32 + am * 16 + g8;
                int cc = n0 + wn * 16 + an * 8 + t4 * 2;
                float bc0 = __ldg(&b1[cc]), bc1 = __ldg(&b1[cc + 1]);
                float v0 = acc[am][an][0] + bc0;
                float v1 = acc[am][an][1] + bc1;
                v0 = (v0 > 0.0f) ? v0 : expm1f(v0);
                v1 = (v1 > 0.0f) ? v1 : expm1f(v1);
                *(__nv_bfloat162*)(sm + F_Y + r * 1040 + cc * 2) = __floats2bfloat162_rn(v0, v1);
                float v2 = acc[am][an][2] + bc0;
                float v3 = acc[am][an][3] + bc1;
                v2 = (v2 > 0.0f) ? v2 : expm1f(v2);
                v3 = (v3 > 0.0f) ? v3 : expm1f(v3);
                *(__nv_bfloat162*)(sm + F_Y + (r + 8) * 1040 + cc * 2) = __floats2bfloat162_rn(v2, v3);
            }
    }
    __syncthreads();

    // ---- stage 2: y2 = ELU(y1 @ W2^T + b2), N=256, K=512 ----
    uint4 breg2[2];
#pragma unroll
    for (int i = 0; i < 2; i++) {
        int u = tid + i * 512;
        int row = u >> 2, q = u & 3;
        breg2[i] = *(const uint4*)(W2b + (size_t)row * M1 + q * 8);
    }
    float acc2[2][4][4];
#pragma unroll
    for (int i = 0; i < 2; i++)
#pragma unroll
        for (int j = 0; j < 4; j++)
#pragma unroll
            for (int k = 0; k < 4; k++) acc2[i][j][k] = 0.0f;

#pragma unroll 1
    for (int c = 0; c < 16; c++) {
        __syncthreads();
#pragma unroll
        for (int i = 0; i < 2; i++) {
            int u = tid + i * 512;
            int row = u >> 2, q = u & 3;
            *(uint4*)(sm + F_B + row * 80 + q * 16) = breg2[i];
        }
        __syncthreads();
        if (c + 1 < 16) {
#pragma unroll
            for (int i = 0; i < 2; i++) {
                int u = tid + i * 512;
                int row = u >> 2, q = u & 3;
                breg2[i] = *(const uint4*)(W2b + (size_t)row * M1 + (c + 1) * 32 + q * 8);
            }
        }
#pragma unroll
        for (int ks = 0; ks < 2; ks++) {
            int s = c * 2 + ks;
            uint32_t a[2][4];
            ldsm4(a[0][0], a[0][1], a[0][2], a[0][3], aB2[0] + s * 32);
            ldsm4(a[1][0], a[1][1], a[1][2], a[1][3], aB2[1] + s * 32);
#pragma unroll
            for (int p = 0; p < 2; p++) {
                uint32_t br0, br1, br2, br3;
                ldsm4(br0, br1, br2, br3, bB2[p] + ks * 32);
#pragma unroll
                for (int am = 0; am < 2; am++) {
                    mma16816(acc2[am][2 * p],     a[am][0], a[am][1], a[am][2], a[am][3], br0, br2);
                    mma16816(acc2[am][2 * p + 1], a[am][0], a[am][1], a[am][2], a[am][3], br1, br3);
                }
            }
        }
    }

    // ---- heads epilogue (block-local) ----
    __syncthreads();                       // all ldsm reads of smA/smY done
    float* ys = (float*)sm;                // 64 x 260 f32 aliases F_A/F_Y
#pragma unroll
    for (int am = 0; am < 2; am++)
#pragma unroll
        for (int an = 0; an < 4; an++) {
            int r = wm * 32 + am * 16 + g8;
            int cc = wn * 32 + an * 8 + t4 * 2;
            float bc0 = __ldg(&b2[cc]), bc1 = __ldg(&b2[cc + 1]);
            float v0 = acc2[am][an][0] + bc0;
            float v1 = acc2[am][an][1] + bc1;
            v0 = (v0 > 0.0f) ? v0 : expm1f(v0);
            v1 = (v1 > 0.0f) ? v1 : expm1f(v1);
            *(float2*)(ys + r * 260 + cc) = make_float2(v0, v1);
            float v2 = acc2[am][an][2] + bc0;
            float v3 = acc2[am][an][3] + bc1;
            v2 = (v2 > 0.0f) ? v2 : expm1f(v2);
            v3 = (v3 > 0.0f) ? v3 : expm1f(v3);
            *(float2*)(ys + (r + 8) * 260 + cc) = make_float2(v2, v3);
        }
    __syncthreads();

    {
        int r = tid >> 3, t8 = tid & 7;
        float dot[3] = {0, 0, 0};
        const float* wr0 = wc + (t8 * 3 + 0) * 260;
        const float* wr1 = wc + (t8 * 3 + 1) * 260;
        const float* wr2 = wc + (t8 * 3 + 2) * 260;
#pragma unroll 8
        for (int k = 0; k < 256; k += 4) {
            float4 yv = *(const float4*)(ys + r * 260 + k);
            float4 w0 = *(const float4*)(wr0 + k);
            float4 w1 = *(const float4*)(wr1 + k);
            float4 w2 = *(const float4*)(wr2 + k);
            dot[0] += yv.x * w0.x + yv.y * w0.y + yv.z * w0.z + yv.w * w0.w;
            dot[1] += yv.x * w1.x + yv.y * w1.y + yv.z * w1.z + yv.w * w1.w;
            dot[2] += yv.x * w2.x + yv.y * w2.y + yv.z * w2.z + yv.w * w2.w;
        }
        float S = 0.0f;
        if (t8 < 4) {
#pragma unroll
            for (int i = 0; i < 3; i++) {
                int o = t8 * 3 + i;
                outF[(m0 + r) * 14 + o] = dot[i] + __ldg(&bm[o]);
            }
        } else {
#pragma unroll
            for (int i = 0; i < 3; i++) {
                int o = (t8 - 4) * 3 + i;
                float l = dot[i] + __ldg(&bsv[o]);
                l = fminf(fmaxf(l, -5.0f), 2.0f);
                S += l;
            }
        }
        S += __shfl_xor_sync(0xffffffffu, S, 1);
        S += __shfl_xor_sync(0xffffffffu, S, 2);
        if (t8 == 4) {
            outF[(m0 + r) * 14 + 12] = -S - 6.0f * LOG2PI;
            outF[(m0 + r) * 14 + 13] = S + 6.0f + 6.0f * LOG2PI;
        }
    }
}

// ---------------- launch ----------------
extern "C" void kernel_launch(void* const* d_in, const int* in_sizes, int n_in,
                              void* d_out, int out_size)
{
    const float *x, *h0, *c0, *W_ih, *W_hh, *b_ih, *b_hh, *ln_g, *ln_b;
    const float *W1, *b1, *W2, *b2, *Wm, *bm, *Ws, *bs;
    const int* done;

    if (in_sizes[1] == TT * BB) {
        // setup_inputs dict order
        x = (const float*)d_in[0];  done = (const int*)d_in[1];
        h0 = (const float*)d_in[2]; c0 = (const float*)d_in[3];
        W_ih = (const float*)d_in[4]; W_hh = (const float*)d_in[5];
        b_ih = (const float*)d_in[6]; b_hh = (const float*)d_in[7];
        ln_g = (const float*)d_in[8]; ln_b = (const float*)d_in[9];
        W1 = (const float*)d_in[10]; b1 = (const float*)d_in[11];
        W2 = (const float*)d_in[12]; b2 = (const float*)d_in[13];
        Wm = (const float*)d_in[14]; bm = (const float*)d_in[15];
        Ws = (const float*)d_in[16]; bs = (const float*)d_in[17];
    } else {
        // reference() signature order
        x = (const float*)d_in[0];
        h0 = (const float*)d_in[1]; c0 = (const float*)d_in[2];
        W_ih = (const float*)d_in[3]; W_hh = (const float*)d_in[4];
        b_ih = (const float*)d_in[5]; b_hh = (const float*)d_in[6];
        ln_g = (const float*)d_in[7]; ln_b = (const float*)d_in[8];
        W1 = (const float*)d_in[9];  b1 = (const float*)d_in[10];
        W2 = (const float*)d_in[11]; b2 = (const float*)d_in[12];
        Wm = (const float*)d_in[13]; bm = (const float*)d_in[14];
        Ws = (const float*)d_in[15]; bs = (const float*)d_in[16];
        done = (const int*)d_in[17];
    }

    float* out = (float*)d_out;

    bf16 *p_hb, *p_W1b, *p_W2b;
    cudaGetSymbolAddress((void**)&p_hb, g_hb);
    cudaGetSymbolAddress((void**)&p_W1b, g_W1b);
    cudaGetSymbolAddress((void**)&p_W2b, g_W2b);

    cudaFuncSetAttribute(lstm_persist, cudaFuncAttributeMaxDynamicSharedMemorySize, SM_TOTAL);
    cudaFuncSetAttribute(mlp_fused, cudaFuncAttributeMaxDynamicSharedMemorySize, F_TOTAL);

    // 0. prep
    prep_wc<<<(G4 * KC + 255) / 256, 256>>>(W_hh, W_ih, b_ih, b_hh);
    prep_w12<<<(M1 * HH + M2 * M1 + 255) / 256, 256>>>(W1, W2);
    prep_x<<<(unsigned)(((size_t)TB * OBS + 255) / 256), 256>>>(x);

    // 1. persistent cluster LSTM (512 threads)
    lstm_persist<<<128, 512, SM_TOTAL>>>(h0, c0, done);

    // 2. fused LN + MLP + heads
    mlp_fused<<<TB / 64, 512, F_TOTAL>>>(p_hb, p_W1b, b1, p_W2b, b2,
                                         ln_g, ln_b, Wm, bm, Ws, bs, out);
}

// round 12
// speedup vs baseline: 1.2385x; 1.2385x over previous
#include <cuda_runtime.h>
#include <cuda_bf16.h>
#include <math.h>
#include <stdint.h>

#define TT 64
#define BB 2048
#define OBS 48
#define HH 256
#define G4 1024
#define KC 304
#define M1 512
#define M2 256
#define TB (TT*BB)
#define LOG2PI 1.8378770664093453f

typedef __nv_bfloat16 bf16;

// ---------------- scratch ----------------
__device__ __align__(16) bf16 g_Wc[G4 * KC];
__device__ float            g_bias[G4];
__device__ __align__(16) bf16 g_W1b[M1 * HH];
__device__ __align__(16) bf16 g_W2b[M2 * M1];
__device__ __align__(16) bf16 g_Whd[32 * M2];        // [Wm|Ws|0] head weights, [o][k]
__device__ __align__(16) bf16 g_xb[(size_t)TB * OBS];
__device__ __align__(16) bf16 g_hb[(size_t)TB * HH];
__device__ float            g_mu[TB];
__device__ float            g_rs[TB];
__device__ __align__(16) bf16 g_y1[(size_t)TB * M1];

// ---------------- helpers ----------------
__device__ __forceinline__ uint32_t bf2_as_u32(__nv_bfloat162 v) {
    return *reinterpret_cast<uint32_t*>(&v);
}

__device__ __forceinline__ void mma16816(float c[4],
    uint32_t a0, uint32_t a1, uint32_t a2, uint32_t a3,
    uint32_t b0, uint32_t b1)
{
    asm volatile(
        "mma.sync.aligned.m16n8k16.row.col.f32.bf16.bf16.f32 "
        "{%0,%1,%2,%3}, {%4,%5,%6,%7}, {%8,%9}, {%0,%1,%2,%3};"
        : "+f"(c[0]), "+f"(c[1]), "+f"(c[2]), "+f"(c[3])
        : "r"(a0), "r"(a1), "r"(a2), "r"(a3), "r"(b0), "r"(b1));
}

__device__ __forceinline__ void ldsm4(uint32_t& r0, uint32_t& r1,
                                      uint32_t& r2, uint32_t& r3, uint32_t addr)
{
    asm volatile("ldmatrix.sync.aligned.m8n8.x4.shared.b16 {%0,%1,%2,%3}, [%4];"
                 : "=r"(r0), "=r"(r1), "=r"(r2), "=r"(r3) : "r"(addr));
}

__device__ __forceinline__ uint32_t smem_u32(const void* p) {
    uint32_t a;
    asm("{ .reg .u64 t; cvta.to.shared.u64 t, %1; cvt.u32.u64 %0, t; }"
        : "=r"(a) : "l"(p));
    return a;
}

__device__ __forceinline__ float tanha(float x) {
    float r; asm("tanh.approx.f32 %0, %1;" : "=f"(r) : "f"(x)); return r;
}
__device__ __forceinline__ float sigm(float x) {
    return fmaf(0.5f, tanha(0.5f * x), 0.5f);
}

// ---------------- prep kernels ----------------
__global__ void prep_wc(const float* __restrict__ W_hh, const float* __restrict__ W_ih,
                        const float* __restrict__ b_ih, const float* __restrict__ b_hh)
{
    int idx = blockIdx.x * blockDim.x + threadIdx.x;
    if (idx >= G4 * KC) return;
    int n = idx / KC, k = idx % KC;
    int g = n & 3, j = n >> 2;
    float v = (k < HH) ? W_hh[(size_t)(g * HH + j) * HH + k]
                       : W_ih[(size_t)(g * HH + j) * OBS + (k - HH)];
    g_Wc[idx] = __float2bfloat16(v);
    if (k == 0) g_bias[n] = b_ih[g * HH + j] + b_hh[g * HH + j];
}

__global__ void prep_w12(const float* __restrict__ W1, const float* __restrict__ W2)
{
    int idx = blockIdx.x * blockDim.x + threadIdx.x;
    if (idx >= M1 * HH + M2 * M1) return;
    if (idx < M1 * HH) {
        int n = idx / HH, k = idx % HH;
        g_W1b[idx] = __float2bfloat16(W1[(size_t)k * M1 + n]);
    } else {
        int i = idx - M1 * HH;
        int n = i / M1, k = i % M1;
        g_W2b[i] = __float2bfloat16(W2[(size_t)k * M2 + n]);
    }
}

__global__ void prep_whd(const float* __restrict__ Wm, const float* __restrict__ Ws)
{
    int idx = blockIdx.x * blockDim.x + threadIdx.x;
    if (idx >= 32 * M2) return;
    int o = idx / M2, k = idx % M2;
    float v = 0.0f;
    if (o < 12) v = Wm[k * 12 + o];
    else if (o < 24) v = Ws[k * 12 + (o - 12)];
    g_Whd[idx] = __float2bfloat16(v);
}

__global__ void prep_x(const float* __restrict__ x)
{
    size_t idx = (size_t)blockIdx.x * blockDim.x + threadIdx.x;
    if (idx < (size_t)TB * OBS) g_xb[idx] = __float2bfloat16(x[idx]);
}

// ---------------- persistent cluster LSTM (256 threads, round-10 proven) ----------------
#define SM_BIAS  0
#define SM_A     1024
#define SM_STAGE 43008
#define SM_B     52224
#define SM_TOTAL 220160
#define ASTR_B 656
#define STG_B  144

__global__ void __launch_bounds__(256, 1) __cluster_dims__(4, 1, 1)
lstm_persist(const float* __restrict__ h0, const float* __restrict__ c0,
             const int* __restrict__ done)
{
    extern __shared__ char smx[];
    const uint32_t smb = smem_u32(smx);

    const int tid = threadIdx.x;
    const int lane = tid & 31, warp = tid >> 5;
    const int wm = warp & 1, wn = warp >> 1;      // 2 x 4 warp grid (m x n)
    const int g8 = lane >> 2, t4 = lane & 3;

    uint32_t rank;
    asm("mov.u32 %0, %%cluster_ctarank;" : "=r"(rank));
    const int b0 = (blockIdx.x >> 2) * 64;
    const int jbase = rank * 64;

    float* bias_s = (float*)(smx + SM_BIAS);
    bias_s[tid] = g_bias[rank * 256 + tid];

    for (int u = tid; u < 256 * 38; u += 256) {
        int n = u / 38, off = u % 38;
        uint4 v = *(const uint4*)((const char*)g_Wc + (size_t)(rank * 256 + n) * 608 + off * 16);
        *(uint4*)(smx + SM_B + n * ASTR_B + off * 16) = v;
    }
    for (int u = tid; u < 4096; u += 256) {
        int row = u >> 6, c4 = u & 63;
        float4 v = *(const float4*)(h0 + (size_t)(b0 + row) * HH + c4 * 4);
        uint2 p;
        p.x = bf2_as_u32(__floats2bfloat162_rn(v.x, v.y));
        p.y = bf2_as_u32(__floats2bfloat162_rn(v.z, v.w));
        *(uint2*)(smx + SM_A + row * ASTR_B + c4 * 8) = p;
    }
    {
        const uint4* xs = (const uint4*)(g_xb + (size_t)b0 * OBS);
        for (int u = tid; u < 384; u += 256) {
            uint4 v = xs[u];
            int e = u * 8, row = e / 48, col = e % 48;
            *(uint4*)(smx + SM_A + row * ASTR_B + 512 + col * 2) = v;
        }
    }
    float creg[16];
#pragma unroll
    for (int am = 0; am < 2; am++)
#pragma unroll
        for (int an = 0; an < 8; an++) {
            int r = wm * 32 + am * 16 + g8 + (t4 & 1) * 8;
            int jl = wn * 16 + an * 2 + (t4 >> 1);
            creg[am * 8 + an] = c0[(size_t)(b0 + r) * HH + jbase + jl];
        }
    __syncthreads();

    const int mi = lane >> 3;
    const int rowoff = ((mi & 1) << 3) + (lane & 7);
    const uint32_t kboff = (uint32_t)((mi >> 1) << 4);
    uint32_t aBase[2], bBase[4];
#pragma unroll
    for (int am = 0; am < 2; am++)
        aBase[am] = smb + SM_A + (wm * 32 + am * 16 + rowoff) * ASTR_B + kboff;
#pragma unroll
    for (int p = 0; p < 4; p++)
        bBase[p] = smb + SM_B + (wn * 64 + p * 16 + rowoff) * ASTR_B + kboff;

    uint32_t peerA[4];
#pragma unroll
    for (int r = 0; r < 4; r++) {
        uint32_t a;
        asm("mapa.shared::cluster.u32 %0, %1, %2;" : "=r"(a) : "r"(smb + SM_A), "r"(r));
        peerA[r] = a;
    }

    const int base_r = wm * 32 + g8;
    int d0, d1, d2, d3;
    {
        const int* dt = done + b0;
        d0 = dt[base_r]; d1 = dt[base_r + 8];
        d2 = dt[base_r + 16]; d3 = dt[base_r + 24];
    }

#pragma unroll 1
    for (int t = 0; t < TT; t++) {
        uint32_t m0 = d0 ? 0u : ~0u, m1 = d1 ? 0u : ~0u;
        uint32_t m2 = d2 ? 0u : ~0u, m3 = d3 ? 0u : ~0u;

        float acc[2][8][4];
#pragma unroll
        for (int i = 0; i < 2; i++)
#pragma unroll
            for (int j = 0; j < 8; j++)
#pragma unroll
                for (int k = 0; k < 4; k++) acc[i][j][k] = 0.0f;

        if (t)
            asm volatile("barrier.cluster.wait.aligned;" ::: "memory");

#pragma unroll
        for (int ch = 0; ch < 19; ch++) {
            uint32_t a[2][4];
            ldsm4(a[0][0], a[0][1], a[0][2], a[0][3], aBase[0] + ch * 32);
            ldsm4(a[1][0], a[1][1], a[1][2], a[1][3], aBase[1] + ch * 32);
            if (ch < 16) {
                a[0][0] &= m0; a[0][2] &= m0; a[0][1] &= m1; a[0][3] &= m1;
                a[1][0] &= m2; a[1][2] &= m2; a[1][1] &= m3; a[1][3] &= m3;
            }
#pragma unroll
            for (int p = 0; p < 4; p++) {
                uint32_t br0, br1, br2, br3;
                ldsm4(br0, br1, br2, br3, bBase[p] + ch * 32);
#pragma unroll
                for (int am = 0; am < 2; am++) {
                    mma16816(acc[am][2 * p],     a[am][0], a[am][1], a[am][2], a[am][3], br0, br2);
                    mma16816(acc[am][2 * p + 1], a[am][0], a[am][1], a[am][2], a[am][3], br1, br3);
                }
            }
        }

        asm volatile("barrier.cluster.arrive.aligned;" ::: "memory");   // B1 arrive

        uint4 xr0, xr1;
        int dn0 = 0, dn1 = 0, dn2 = 0, dn3 = 0;
        const bool hx = (t < TT - 1);
        if (hx) {
            const uint4* xs = (const uint4*)(g_xb + ((size_t)(t + 1) * BB + b0) * OBS);
            xr0 = xs[tid];
            if (tid < 128) xr1 = xs[tid + 256];
            const int* dt = done + (size_t)(t + 1) * BB + b0;
            dn0 = dt[base_r]; dn1 = dt[base_r + 8];
            dn2 = dt[base_r + 16]; dn3 = dt[base_r + 24];
        }

        const bool odd = (t4 & 1);
#pragma unroll
        for (int am = 0; am < 2; am++) {
            const int dlo = (am == 0) ? d0 : d2;
            const int dhi = (am == 0) ? d1 : d3;
            const int dflag = odd ? dhi : dlo;
#pragma unroll
            for (int an = 0; an < 8; an++) {
                float* a = acc[am][an];
                float s0 = odd ? a[0] : a[2];
                float s1 = odd ? a[1] : a[3];
                float e0 = __shfl_xor_sync(0xffffffffu, s0, 1);
                float e1 = __shfl_xor_sync(0xffffffffu, s1, 1);
                float q0 = odd ? e0 : a[0];
                float q1 = odd ? e1 : a[1];
                float q2 = odd ? a[2] : e0;
                float q3 = odd ? a[3] : e1;
                int jl = wn * 16 + an * 2 + (t4 >> 1);
                float4 bb = *(const float4*)&bias_s[jl * 4];
                float gi = q0 + bb.x, gf = q1 + bb.y, gg = q2 + bb.z, go = q3 + bb.w;
                int cell = am * 8 + an;
                float cold = dflag ? 0.0f : creg[cell];
                float cn = sigm(gf) * cold + sigm(gi) * tanha(gg);
                creg[cell] = cn;
                float hn = sigm(go) * tanha(cn);
                int r = wm * 32 + am * 16 + g8 + (odd ? 8 : 0);
                *(bf16*)(smx + SM_STAGE + r * STG_B + jl * 2) = __float2bfloat16(hn);
            }
        }

        if (hx) {
            int e = tid * 8;
            *(uint4*)(smx + SM_A + (e / 48) * ASTR_B + 512 + (e % 48) * 2) = xr0;
            if (tid < 128) {
                int e2 = (tid + 256) * 8;
                *(uint4*)(smx + SM_A + (e2 / 48) * ASTR_B + 512 + (e2 % 48) * 2) = xr1;
            }
        }

        __syncthreads();
        asm volatile("barrier.cluster.wait.aligned;" ::: "memory");     // B1 wait

#pragma unroll
        for (int q = 0; q < 2; q++) {
            int u = tid + q * 256;
            int row = u >> 3, off = u & 7;
            uint4 v = *(const uint4*)(smx + SM_STAGE + row * STG_B + off * 16);
#pragma unroll
            for (int r = 0; r < 4; r++) {
                uint32_t da = peerA[r] + row * ASTR_B + jbase * 2 + off * 16;
                asm volatile("st.shared::cluster.v4.b32 [%0], {%1,%2,%3,%4};"
                             :: "r"(da), "r"(v.x), "r"(v.y), "r"(v.z), "r"(v.w) : "memory");
            }
            *(uint4*)(g_hb + ((size_t)t * BB + b0 + row) * HH + jbase + off * 8) = v;
        }

        asm volatile("barrier.cluster.arrive.aligned;" ::: "memory");   // B2 arrive
        d0 = dn0; d1 = dn1; d2 = dn2; d3 = dn3;
    }
    asm volatile("barrier.cluster.wait.aligned;" ::: "memory");
}

// ---------------- LayerNorm stats ----------------
__global__ __launch_bounds__(256) void ln_stats()
{
    int row = blockIdx.x * 8 + (threadIdx.x >> 5);
    int lane = threadIdx.x & 31;
    uint4 u = *(const uint4*)(g_hb + (size_t)row * HH + lane * 8);
    const __nv_bfloat162* p = (const __nv_bfloat162*)&u;
    float s = 0.0f, s2 = 0.0f;
#pragma unroll
    for (int i = 0; i < 4; i++) {
        float2 f = __bfloat1622float2(p[i]);
        s += f.x + f.y;
        s2 += f.x * f.x + f.y * f.y;
    }
#pragma unroll
    for (int o = 16; o; o >>= 1) {
        s  += __shfl_xor_sync(0xffffffffu, s, o);
        s2 += __shfl_xor_sync(0xffffffffu, s2, o);
    }
    if (lane == 0) {
        float mu = s * (1.0f / HH);
        float var = s2 * (1.0f / HH) - mu * mu;
        g_mu[row] = mu;
        g_rs[row] = rsqrtf(var + 1e-5f);
    }
}

// ---------------- A-hot GEMM (round-10 core; HEADS epilogue now tensor-core) ----------------
template <int KD, int NT, bool LNA, bool HEADS>
__global__ __launch_bounds__(256) void gemm_hot(
    const bf16* __restrict__ A, const bf16* __restrict__ Bw,
    const float* __restrict__ bias, bf16* __restrict__ Out,
    const float* __restrict__ gamma, const float* __restrict__ beta,
    const float* __restrict__ bm, const float* __restrict__ bsv,
    float* __restrict__ outF)
{
    constexpr int AST = KD + 8;
    constexpr int ASZ = 64 * AST * 2;
    constexpr int P   = NT / 64;
    constexpr int AN  = NT / 32;
    constexpr int CH  = KD / 32;
    constexpr int BLD = NT / 64;

    extern __shared__ char sm[];
    char* smA = sm;
    char* smB = sm + ASZ;
    char* smW = sm + ASZ + NT * 80;          // HEADS only: 32 x 528B

    const int tid = threadIdx.x;
    const int lane = tid & 31, warp = tid >> 5;
    const int wm = warp & 1, wn = warp >> 1;
    const int g8 = lane >> 2, t4 = lane & 3;
    const size_t m0 = (size_t)blockIdx.x * 64;
    const int n0 = blockIdx.y * NT;

    // ---- load A tile (once), LN fused ----
    for (int u = tid; u < 64 * (KD / 8); u += 256) {
        int row = u / (KD / 8), pos = u % (KD / 8);
        uint4 v = *(const uint4*)(A + (m0 + row) * KD + pos * 8);
        if (LNA) {
            float mu = g_mu[m0 + row], rs = g_rs[m0 + row];
            __nv_bfloat162* vp = (__nv_bfloat162*)&v;
            int kb = pos * 8;
#pragma unroll
            for (int q = 0; q < 4; q++) {
                float2 f = __bfloat1622float2(vp[q]);
                f.x = (f.x - mu) * rs * __ldg(&gamma[kb + 2 * q])     + __ldg(&beta[kb + 2 * q]);
                f.y = (f.y - mu) * rs * __ldg(&gamma[kb + 2 * q + 1]) + __ldg(&beta[kb + 2 * q + 1]);
                vp[q] = __floats2bfloat162_rn(f.x, f.y);
            }
        }
        *(uint4*)(smA + row * AST * 2 + pos * 16) = v;
    }
    if (HEADS) {
        // head weights [32][256] bf16 -> smW, stride 528B
        for (int u = tid; u < 1024; u += 256) {
            int row = u >> 5, q = u & 31;
            *(uint4*)(smW + row * 528 + q * 16) = *(const uint4*)(g_Whd + row * M2 + q * 8);
        }
    }

    uint4 breg[BLD];
#pragma unroll
    for (int i = 0; i < BLD; i++) {
        int u = tid + i * 256;
        int row = u >> 2, q = u & 3;
        breg[i] = *(const uint4*)(Bw + (size_t)(n0 + row) * KD + q * 8);
    }

    float acc[2][AN][4];
#pragma unroll
    for (int i = 0; i < 2; i++)
#pragma unroll
        for (int j = 0; j < AN; j++)
#pragma unroll
            for (int k = 0; k < 4; k++) acc[i][j][k] = 0.0f;

    const int mi = lane >> 3;
    const int rowoff = ((mi & 1) << 3) + (lane & 7);
    const uint32_t kb16 = (uint32_t)((mi >> 1) << 4);
    const uint32_t smAu = smem_u32(smA);
    const uint32_t smBu = smem_u32(smB);
    uint32_t aB[2], bB[P];
#pragma unroll
    for (int am = 0; am < 2; am++)
        aB[am] = smAu + (wm * 32 + am * 16 + rowoff) * (AST * 2) + kb16;
#pragma unroll
    for (int p = 0; p < P; p++)
        bB[p] = smBu + (wn * (NT / 4) + p * 16 + rowoff) * 80 + kb16;

#pragma unroll 1
    for (int c = 0; c < CH; c++) {
        __syncthreads();
#pragma unroll
        for (int i = 0; i < BLD; i++) {
            int u = tid + i * 256;
            int row = u >> 2, q = u & 3;
            *(uint4*)(smB + row * 80 + q * 16) = breg[i];
        }
        __syncthreads();
        if (c + 1 < CH) {
#pragma unroll
            for (int i = 0; i < BLD; i++) {
                int u = tid + i * 256;
                int row = u >> 2, q = u & 3;
                breg[i] = *(const uint4*)(Bw + (size_t)(n0 + row) * KD + (c + 1) * 32 + q * 8);
            }
        }
#pragma unroll
        for (int ks = 0; ks < 2; ks++) {
            int s = c * 2 + ks;
            uint32_t a[2][4];
            ldsm4(a[0][0], a[0][1], a[0][2], a[0][3], aB[0] + s * 32);
            ldsm4(a[1][0], a[1][1], a[1][2], a[1][3], aB[1] + s * 32);
#pragma unroll
            for (int p = 0; p < P; p++) {
                uint32_t br0, br1, br2, br3;
                ldsm4(br0, br1, br2, br3, bB[p] + ks * 32);
#pragma unroll
                for (int am = 0; am < 2; am++) {
                    mma16816(acc[am][2 * p],     a[am][0], a[am][1], a[am][2], a[am][3], br0, br2);
                    mma16816(acc[am][2 * p + 1], a[am][0], a[am][1], a[am][2], a[am][3], br1, br3);
                }
            }
        }
    }

    if (!HEADS) {
#pragma unroll
        for (int am = 0; am < 2; am++)
#pragma unroll
            for (int an = 0; an < AN; an++) {
                size_t r = m0 + wm * 32 + am * 16 + g8;
                int c = n0 + wn * (NT / 4) + an * 8 + t4 * 2;
                float bc0 = __ldg(&bias[c]), bc1 = __ldg(&bias[c + 1]);
                float v0 = acc[am][an][0] + bc0;
                float v1 = acc[am][an][1] + bc1;
                v0 = (v0 > 0.0f) ? v0 : expm1f(v0);
                v1 = (v1 > 0.0f) ? v1 : expm1f(v1);
                *(__nv_bfloat162*)(Out + r * (M1) + c) = __floats2bfloat162_rn(v0, v1);
                float v2 = acc[am][an][2] + bc0;
                float v3 = acc[am][an][3] + bc1;
                v2 = (v2 > 0.0f) ? v2 : expm1f(v2);
                v3 = (v3 > 0.0f) ? v3 : expm1f(v3);
                *(__nv_bfloat162*)(Out + (r + 8) * (M1) + c) = __floats2bfloat162_rn(v2, v3);
            }
    } else {
        // ---- tensor-core heads epilogue ----
        __syncthreads();                     // all ldsm reads of smA done
        // y2 (ELU, bf16) -> ys aliasing smA, stride 528B (conflict-free)
        char* ys = smA;
#pragma unroll
        for (int am = 0; am < 2; am++)
#pragma unroll
            for (int an = 0; an < AN; an++) {
                int r = wm * 32 + am * 16 + g8;
                int c = wn * (NT / 4) + an * 8 + t4 * 2;
                float bc0 = __ldg(&bias[c]), bc1 = __ldg(&bias[c + 1]);
                float v0 = acc[am][an][0] + bc0;
                float v1 = acc[am][an][1] + bc1;
                v0 = (v0 > 0.0f) ? v0 : expm1f(v0);
                v1 = (v1 > 0.0f) ? v1 : expm1f(v1);
                *(__nv_bfloat162*)(ys + r * 528 + c * 2) = __floats2bfloat162_rn(v0, v1);
                float v2 = acc[am][an][2] + bc0;
                float v3 = acc[am][an][3] + bc1;
                v2 = (v2 > 0.0f) ? v2 : expm1f(v2);
                v3 = (v3 > 0.0f) ? v3 : expm1f(v3);
                *(__nv_bfloat162*)(ys + (r + 8) * 528 + c * 2) = __floats2bfloat162_rn(v2, v3);
            }
        __syncthreads();

        if (warp < 4) {
            // warp w: rows [16w, 16w+16), N=32 head cols, K=256
            const uint32_t aH = smem_u32(ys) + (warp * 16 + rowoff) * 528 + kb16;
            const uint32_t smWu = smem_u32(smW);
            const uint32_t bH0 = smWu + rowoff * 528 + kb16;
            const uint32_t bH1 = smWu + (16 + rowoff) * 528 + kb16;

            float ah[4][4];
#pragma unroll
            for (int i = 0; i < 4; i++)
#pragma unroll
                for (int k = 0; k < 4; k++) ah[i][k] = 0.0f;

#pragma unroll
            for (int s = 0; s < 16; s++) {
                uint32_t a0, a1, a2, a3;
                ldsm4(a0, a1, a2, a3, aH + s * 32);
                uint32_t b0, b1, b2, b3;
                ldsm4(b0, b1, b2, b3, bH0 + s * 32);
                mma16816(ah[0], a0, a1, a2, a3, b0, b2);
                mma16816(ah[1], a0, a1, a2, a3, b1, b3);
                ldsm4(b0, b1, b2, b3, bH1 + s * 32);
                mma16816(ah[2], a0, a1, a2, a3, b0, b2);
                mma16816(ah[3], a0, a1, a2, a3, b1, b3);
            }

            int r = warp * 16 + g8;
            float Slo = 0.0f, Shi = 0.0f;
#pragma unroll
            for (int an = 0; an < 4; an++)
#pragma unroll
                for (int j = 0; j < 2; j++) {
                    int o = an * 8 + t4 * 2 + j;
                    float vlo = ah[an][j], vhi = ah[an][2 + j];
                    if (o < 12) {
                        float bb = __ldg(&bm[o]);
                        outF[(m0 + r) * 14 + o]     = vlo + bb;
                        outF[(m0 + r + 8) * 14 + o] = vhi + bb;
                    } else if (o < 24) {
                        float bb = __ldg(&bsv[o - 12]);
                        Slo += fminf(fmaxf(vlo + bb, -5.0f), 2.0f);
                        Shi += fminf(fmaxf(vhi + bb, -5.0f), 2.0f);
                    }
                }
            Slo += __shfl_xor_sync(0xffffffffu, Slo, 1);
            Slo += __shfl_xor_sync(0xffffffffu, Slo, 2);
            Shi += __shfl_xor_sync(0xffffffffu, Shi, 1);
            Shi += __shfl_xor_sync(0xffffffffu, Shi, 2);
            if (t4 == 0) {
                outF[(m0 + r) * 14 + 12]     = -Slo - 6.0f * LOG2PI;
                outF[(m0 + r) * 14 + 13]     = Slo + 6.0f + 6.0f * LOG2PI;
                outF[(m0 + r + 8) * 14 + 12] = -Shi - 6.0f * LOG2PI;
                outF[(m0 + r + 8) * 14 + 13] = Shi + 6.0f + 6.0f * LOG2PI;
            }
        }
    }
}

// ---------------- launch ----------------
extern "C" void kernel_launch(void* const* d_in, const int* in_sizes, int n_in,
                              void* d_out, int out_size)
{
    const float *x, *h0, *c0, *W_ih, *W_hh, *b_ih, *b_hh, *ln_g, *ln_b;
    const float *W1, *b1, *W2, *b2, *Wm, *bm, *Ws, *bs;
    const int* done;

    if (in_sizes[1] == TT * BB) {
        // setup_inputs dict order
        x = (const float*)d_in[0];  done = (const int*)d_in[1];
        h0 = (const float*)d_in[2]; c0 = (const float*)d_in[3];
        W_ih = (const float*)d_in[4]; W_hh = (const float*)d_in[5];
        b_ih = (const float*)d_in[6]; b_hh = (const float*)d_in[7];
        ln_g = (const float*)d_in[8]; ln_b = (const float*)d_in[9];
        W1 = (const float*)d_in[10]; b1 = (const float*)d_in[11];
        W2 = (const float*)d_in[12]; b2 = (const float*)d_in[13];
        Wm = (const float*)d_in[14]; bm = (const float*)d_in[15];
        Ws = (const float*)d_in[16]; bs = (const float*)d_in[17];
    } else {
        // reference() signature order
        x = (const float*)d_in[0];
        h0 = (const float*)d_in[1]; c0 = (const float*)d_in[2];
        W_ih = (const float*)d_in[3]; W_hh = (const float*)d_in[4];
        b_ih = (const float*)d_in[5]; b_hh = (const float*)d_in[6];
        ln_g = (const float*)d_in[7]; ln_b = (const float*)d_in[8];
        W1 = (const float*)d_in[9];  b1 = (const float*)d_in[10];
        W2 = (const float*)d_in[11]; b2 = (const float*)d_in[12];
        Wm = (const float*)d_in[13]; bm = (const float*)d_in[14];
        Ws = (const float*)d_in[15]; bs = (const float*)d_in[16];
        done = (const int*)d_in[17];
    }

    float* out = (float*)d_out;

    bf16 *p_hb, *p_W1b, *p_W2b, *p_y1;
    cudaGetSymbolAddress((void**)&p_hb, g_hb);
    cudaGetSymbolAddress((void**)&p_W1b, g_W1b);
    cudaGetSymbolAddress((void**)&p_W2b, g_W2b);
    cudaGetSymbolAddress((void**)&p_y1, g_y1);

    const int SM1 = 64 * (HH + 8) * 2 + 128 * 80;                 // 44032
    const int SM2 = 64 * (M1 + 8) * 2 + 256 * 80 + 32 * 528;      // 103936

    cudaFuncSetAttribute(lstm_persist, cudaFuncAttributeMaxDynamicSharedMemorySize, SM_TOTAL);
    cudaFuncSetAttribute(gemm_hot<HH, 128, true, false>,
                         cudaFuncAttributeMaxDynamicSharedMemorySize, SM1);
    cudaFuncSetAttribute(gemm_hot<M1, 256, false, true>,
                         cudaFuncAttributeMaxDynamicSharedMemorySize, SM2);

    // 0. prep
    prep_wc<<<(G4 * KC + 255) / 256, 256>>>(W_hh, W_ih, b_ih, b_hh);
    prep_w12<<<(M1 * HH + M2 * M1 + 255) / 256, 256>>>(W1, W2);
    prep_whd<<<(32 * M2 + 255) / 256, 256>>>(Wm, Ws);
    prep_x<<<(unsigned)(((size_t)TB * OBS + 255) / 256), 256>>>(x);

    // 1. persistent cluster LSTM
    lstm_persist<<<128, 256, SM_TOTAL>>>(h0, c0, done);

    // 2. LN stats
    ln_stats<<<TB / 8, 256>>>();

    // 3. MLP1
    gemm_hot<HH, 128, true, false><<<dim3(TB / 64, M1 / 128), 256, SM1>>>(
        p_hb, p_W1b, b1, p_y1, ln_g, ln_b, nullptr, nullptr, nullptr);

    // 4. MLP2 + tensor-core heads
    gemm_hot<M1, 256, false, true><<<dim3(TB / 64, 1), 256, SM2>>>(
        p_y1, p_W2b, b2, nullptr, nullptr, nullptr, bm, bs, out);
}

// round 13
// speedup vs baseline: 1.2876x; 1.0396x over previous
#include <cuda_runtime.h>
#include <cuda_bf16.h>
#include <math.h>
#include <stdint.h>

#define TT 64
#define BB 2048
#define OBS 48
#define HH 256
#define G4 1024
#define KC 304
#define M1 512
#define M2 256
#define TB (TT*BB)
#define LOG2PI 1.8378770664093453f

typedef __nv_bfloat16 bf16;

// ---------------- scratch ----------------
__device__ __align__(16) bf16 g_Wc[G4 * KC];
__device__ float            g_bias[G4];
__device__ __align__(16) bf16 g_W1b[M1 * HH];
__device__ __align__(16) bf16 g_W2b[M2 * M1];
__device__ __align__(16) bf16 g_Whd[32 * M2];        // [Wm|Ws|0] head weights, [o][k]
__device__ __align__(16) bf16 g_xb[(size_t)TB * OBS];
__device__ __align__(16) bf16 g_hb[(size_t)TB * HH];
__device__ __align__(16) bf16 g_y1[(size_t)TB * M1];

// ---------------- helpers ----------------
__device__ __forceinline__ uint32_t bf2_as_u32(__nv_bfloat162 v) {
    return *reinterpret_cast<uint32_t*>(&v);
}

__device__ __forceinline__ void mma16816(float c[4],
    uint32_t a0, uint32_t a1, uint32_t a2, uint32_t a3,
    uint32_t b0, uint32_t b1)
{
    asm volatile(
        "mma.sync.aligned.m16n8k16.row.col.f32.bf16.bf16.f32 "
        "{%0,%1,%2,%3}, {%4,%5,%6,%7}, {%8,%9}, {%0,%1,%2,%3};"
        : "+f"(c[0]), "+f"(c[1]), "+f"(c[2]), "+f"(c[3])
        : "r"(a0), "r"(a1), "r"(a2), "r"(a3), "r"(b0), "r"(b1));
}

__device__ __forceinline__ void ldsm4(uint32_t& r0, uint32_t& r1,
                                      uint32_t& r2, uint32_t& r3, uint32_t addr)
{
    asm volatile("ldmatrix.sync.aligned.m8n8.x4.shared.b16 {%0,%1,%2,%3}, [%4];"
                 : "=r"(r0), "=r"(r1), "=r"(r2), "=r"(r3) : "r"(addr));
}

__device__ __forceinline__ uint32_t smem_u32(const void* p) {
    uint32_t a;
    asm("{ .reg .u64 t; cvta.to.shared.u64 t, %1; cvt.u32.u64 %0, t; }"
        : "=r"(a) : "l"(p));
    return a;
}

__device__ __forceinline__ float tanha(float x) {
    float r; asm("tanh.approx.f32 %0, %1;" : "=f"(r) : "f"(x)); return r;
}
__device__ __forceinline__ float sigm(float x) {
    return fmaf(0.5f, tanha(0.5f * x), 0.5f);
}

// ---------------- merged prep kernel ----------------
// segment layout (threads): [0, XSEG) x convert (4 elems/thread),
// [XSEG, +WCSEG) combined LSTM weights, [.. +W12SEG) W1/W2, [.. +WHDSEG) heads.
#define XSEG   ((TB * OBS) / 4)                 // 1572864
#define WCSEG  (G4 * KC)                        // 311296
#define W12SEG (M1 * HH + M2 * M1)              // 262144
#define WHDSEG (32 * M2)                        // 8192
#define PREP_TOTAL (XSEG + WCSEG + W12SEG + WHDSEG)

__global__ void prep_all(
    const float* __restrict__ x,
    const float* __restrict__ W_hh, const float* __restrict__ W_ih,
    const float* __restrict__ b_ih, const float* __restrict__ b_hh,
    const float* __restrict__ W1, const float* __restrict__ W2,
    const float* __restrict__ Wm, const float* __restrict__ Ws)
{
    int idx = blockIdx.x * blockDim.x + threadIdx.x;
    if (idx < XSEG) {
        float4 v = *(const float4*)(x + (size_t)idx * 4);
        uint2 p;
        p.x = bf2_as_u32(__floats2bfloat162_rn(v.x, v.y));
        p.y = bf2_as_u32(__floats2bfloat162_rn(v.z, v.w));
        *(uint2*)(g_xb + (size_t)idx * 4) = p;
        return;
    }
    idx -= XSEG;
    if (idx < WCSEG) {
        int n = idx / KC, k = idx % KC;
        int g = n & 3, j = n >> 2;
        float v = (k < HH) ? W_hh[(size_t)(g * HH + j) * HH + k]
                           : W_ih[(size_t)(g * HH + j) * OBS + (k - HH)];
        g_Wc[idx] = __float2bfloat16(v);
        if (k == 0) g_bias[n] = b_ih[g * HH + j] + b_hh[g * HH + j];
        return;
    }
    idx -= WCSEG;
    if (idx < W12SEG) {
        if (idx < M1 * HH) {
            int n = idx / HH, k = idx % HH;
            g_W1b[idx] = __float2bfloat16(W1[(size_t)k * M1 + n]);
        } else {
            int i = idx - M1 * HH;
            int n = i / M1, k = i % M1;
            g_W2b[i] = __float2bfloat16(W2[(size_t)k * M2 + n]);
        }
        return;
    }
    idx -= W12SEG;
    if (idx < WHDSEG) {
        int o = idx / M2, k = idx % M2;
        float v = 0.0f;
        if (o < 12) v = Wm[k * 12 + o];
        else if (o < 24) v = Ws[k * 12 + (o - 12)];
        g_Whd[idx] = __float2bfloat16(v);
    }
}

// ---------------- persistent cluster LSTM (proven round-10/12 version) ----------------
#define SM_BIAS  0
#define SM_A     1024
#define SM_STAGE 43008
#define SM_B     52224
#define SM_TOTAL 220160
#define ASTR_B 656
#define STG_B  144

__global__ void __launch_bounds__(256, 1) __cluster_dims__(4, 1, 1)
lstm_persist(const float* __restrict__ h0, const float* __restrict__ c0,
             const int* __restrict__ done)
{
    extern __shared__ char smx[];
    const uint32_t smb = smem_u32(smx);

    const int tid = threadIdx.x;
    const int lane = tid & 31, warp = tid >> 5;
    const int wm = warp & 1, wn = warp >> 1;
    const int g8 = lane >> 2, t4 = lane & 3;

    uint32_t rank;
    asm("mov.u32 %0, %%cluster_ctarank;" : "=r"(rank));
    const int b0 = (blockIdx.x >> 2) * 64;
    const int jbase = rank * 64;

    float* bias_s = (float*)(smx + SM_BIAS);
    bias_s[tid] = g_bias[rank * 256 + tid];

    for (int u = tid; u < 256 * 38; u += 256) {
        int n = u / 38, off = u % 38;
        uint4 v = *(const uint4*)((const char*)g_Wc + (size_t)(rank * 256 + n) * 608 + off * 16);
        *(uint4*)(smx + SM_B + n * ASTR_B + off * 16) = v;
    }
    for (int u = tid; u < 4096; u += 256) {
        int row = u >> 6, c4 = u & 63;
        float4 v = *(const float4*)(h0 + (size_t)(b0 + row) * HH + c4 * 4);
        uint2 p;
        p.x = bf2_as_u32(__floats2bfloat162_rn(v.x, v.y));
        p.y = bf2_as_u32(__floats2bfloat162_rn(v.z, v.w));
        *(uint2*)(smx + SM_A + row * ASTR_B + c4 * 8) = p;
    }
    {
        const uint4* xs = (const uint4*)(g_xb + (size_t)b0 * OBS);
        for (int u = tid; u < 384; u += 256) {
            uint4 v = xs[u];
            int e = u * 8, row = e / 48, col = e % 48;
            *(uint4*)(smx + SM_A + row * ASTR_B + 512 + col * 2) = v;
        }
    }
    float creg[16];
#pragma unroll
    for (int am = 0; am < 2; am++)
#pragma unroll
        for (int an = 0; an < 8; an++) {
            int r = wm * 32 + am * 16 + g8 + (t4 & 1) * 8;
            int jl = wn * 16 + an * 2 + (t4 >> 1);
            creg[am * 8 + an] = c0[(size_t)(b0 + r) * HH + jbase + jl];
        }
    __syncthreads();

    const int mi = lane >> 3;
    const int rowoff = ((mi & 1) << 3) + (lane & 7);
    const uint32_t kboff = (uint32_t)((mi >> 1) << 4);
    uint32_t aBase[2], bBase[4];
#pragma unroll
    for (int am = 0; am < 2; am++)
        aBase[am] = smb + SM_A + (wm * 32 + am * 16 + rowoff) * ASTR_B + kboff;
#pragma unroll
    for (int p = 0; p < 4; p++)
        bBase[p] = smb + SM_B + (wn * 64 + p * 16 + rowoff) * ASTR_B + kboff;

    uint32_t peerA[4];
#pragma unroll
    for (int r = 0; r < 4; r++) {
        uint32_t a;
        asm("mapa.shared::cluster.u32 %0, %1, %2;" : "=r"(a) : "r"(smb + SM_A), "r"(r));
        peerA[r] = a;
    }

    const int base_r = wm * 32 + g8;
    int d0, d1, d2, d3;
    {
        const int* dt = done + b0;
        d0 = dt[base_r]; d1 = dt[base_r + 8];
        d2 = dt[base_r + 16]; d3 = dt[base_r + 24];
    }

#pragma unroll 1
    for (int t = 0; t < TT; t++) {
        uint32_t m0 = d0 ? 0u : ~0u, m1 = d1 ? 0u : ~0u;
        uint32_t m2 = d2 ? 0u : ~0u, m3 = d3 ? 0u : ~0u;

        float acc[2][8][4];
#pragma unroll
        for (int i = 0; i < 2; i++)
#pragma unroll
            for (int j = 0; j < 8; j++)
#pragma unroll
                for (int k = 0; k < 4; k++) acc[i][j][k] = 0.0f;

        if (t)
            asm volatile("barrier.cluster.wait.aligned;" ::: "memory");

#pragma unroll
        for (int ch = 0; ch < 19; ch++) {
            uint32_t a[2][4];
            ldsm4(a[0][0], a[0][1], a[0][2], a[0][3], aBase[0] + ch * 32);
            ldsm4(a[1][0], a[1][1], a[1][2], a[1][3], aBase[1] + ch * 32);
            if (ch < 16) {
                a[0][0] &= m0; a[0][2] &= m0; a[0][1] &= m1; a[0][3] &= m1;
                a[1][0] &= m2; a[1][2] &= m2; a[1][1] &= m3; a[1][3] &= m3;
            }
#pragma unroll
            for (int p = 0; p < 4; p++) {
                uint32_t br0, br1, br2, br3;
                ldsm4(br0, br1, br2, br3, bBase[p] + ch * 32);
#pragma unroll
                for (int am = 0; am < 2; am++) {
                    mma16816(acc[am][2 * p],     a[am][0], a[am][1], a[am][2], a[am][3], br0, br2);
                    mma16816(acc[am][2 * p + 1], a[am][0], a[am][1], a[am][2], a[am][3], br1, br3);
                }
            }
        }

        asm volatile("barrier.cluster.arrive.aligned;" ::: "memory");   // B1 arrive

        uint4 xr0, xr1;
        int dn0 = 0, dn1 = 0, dn2 = 0, dn3 = 0;
        const bool hx = (t < TT - 1);
        if (hx) {
            const uint4* xs = (const uint4*)(g_xb + ((size_t)(t + 1) * BB + b0) * OBS);
            xr0 = xs[tid];
            if (tid < 128) xr1 = xs[tid + 256];
            const int* dt = done + (size_t)(t + 1) * BB + b0;
            dn0 = dt[base_r]; dn1 = dt[base_r + 8];
            dn2 = dt[base_r + 16]; dn3 = dt[base_r + 24];
        }

        const bool odd = (t4 & 1);
#pragma unroll
        for (int am = 0; am < 2; am++) {
            const int dlo = (am == 0) ? d0 : d2;
            const int dhi = (am == 0) ? d1 : d3;
            const int dflag = odd ? dhi : dlo;
#pragma unroll
            for (int an = 0; an < 8; an++) {
                float* a = acc[am][an];
                float s0 = odd ? a[0] : a[2];
                float s1 = odd ? a[1] : a[3];
                float e0 = __shfl_xor_sync(0xffffffffu, s0, 1);
                float e1 = __shfl_xor_sync(0xffffffffu, s1, 1);
                float q0 = odd ? e0 : a[0];
                float q1 = odd ? e1 : a[1];
                float q2 = odd ? a[2] : e0;
                float q3 = odd ? a[3] : e1;
                int jl = wn * 16 + an * 2 + (t4 >> 1);
                float4 bb = *(const float4*)&bias_s[jl * 4];
                float gi = q0 + bb.x, gf = q1 + bb.y, gg = q2 + bb.z, go = q3 + bb.w;
                int cell = am * 8 + an;
                float cold = dflag ? 0.0f : creg[cell];
                float cn = sigm(gf) * cold + sigm(gi) * tanha(gg);
                creg[cell] = cn;
                float hn = sigm(go) * tanha(cn);
                int r = wm * 32 + am * 16 + g8 + (odd ? 8 : 0);
                *(bf16*)(smx + SM_STAGE + r * STG_B + jl * 2) = __float2bfloat16(hn);
            }
        }

        if (hx) {
            int e = tid * 8;
            *(uint4*)(smx + SM_A + (e / 48) * ASTR_B + 512 + (e % 48) * 2) = xr0;
            if (tid < 128) {
                int e2 = (tid + 256) * 8;
                *(uint4*)(smx + SM_A + (e2 / 48) * ASTR_B + 512 + (e2 % 48) * 2) = xr1;
            }
        }

        __syncthreads();
        asm volatile("barrier.cluster.wait.aligned;" ::: "memory");     // B1 wait

#pragma unroll
        for (int q = 0; q < 2; q++) {
            int u = tid + q * 256;
            int row = u >> 3, off = u & 7;
            uint4 v = *(const uint4*)(smx + SM_STAGE + row * STG_B + off * 16);
#pragma unroll
            for (int r = 0; r < 4; r++) {
                uint32_t da = peerA[r] + row * ASTR_B + jbase * 2 + off * 16;
                asm volatile("st.shared::cluster.v4.b32 [%0], {%1,%2,%3,%4};"
                             :: "r"(da), "r"(v.x), "r"(v.y), "r"(v.z), "r"(v.w) : "memory");
            }
            *(uint4*)(g_hb + ((size_t)t * BB + b0 + row) * HH + jbase + off * 8) = v;
        }

        asm volatile("barrier.cluster.arrive.aligned;" ::: "memory");   // B2 arrive
        d0 = dn0; d1 = dn1; d2 = dn2; d3 = dn3;
    }
    asm volatile("barrier.cluster.wait.aligned;" ::: "memory");
}

// ---------------- A-hot GEMM; LN computed in-kernel when LNA ----------------
template <int KD, int NT, bool LNA, bool HEADS>
__global__ __launch_bounds__(256) void gemm_hot(
    const bf16* __restrict__ A, const bf16* __restrict__ Bw,
    const float* __restrict__ bias, bf16* __restrict__ Out,
    const float* __restrict__ gamma, const float* __restrict__ beta,
    const float* __restrict__ bm, const float* __restrict__ bsv,
    float* __restrict__ outF)
{
    constexpr int AST = KD + 8;
    constexpr int ASZ = 64 * AST * 2;
    constexpr int P   = NT / 64;
    constexpr int AN  = NT / 32;
    constexpr int CH  = KD / 32;
    constexpr int BLD = NT / 64;

    extern __shared__ char sm[];
    char* smA = sm;
    char* smB = sm + ASZ;
    char* smW = sm + ASZ + NT * 80;          // HEADS only: 32 x 528B

    const int tid = threadIdx.x;
    const int lane = tid & 31, warp = tid >> 5;
    const int wm = warp & 1, wn = warp >> 1;
    const int g8 = lane >> 2, t4 = lane & 3;
    const size_t m0 = (size_t)blockIdx.x * 64;
    const int n0 = blockIdx.y * NT;

    // ---- load A tile (once); LN computed in-kernel if LNA ----
    if (LNA) {
        // KD==256: iteration it covers row = warp + it*8 entirely within one warp.
#pragma unroll
        for (int it = 0; it < 64 * (KD / 8) / 256; it++) {
            int u = tid + it * 256;
            int row = u >> 5, pos = u & 31;
            uint4 v = *(const uint4*)(A + (m0 + row) * KD + pos * 8);
            __nv_bfloat162* vp = (__nv_bfloat162*)&v;
            float f[8];
#pragma unroll
            for (int q = 0; q < 4; q++) {
                float2 t2 = __bfloat1622float2(vp[q]);
                f[2 * q] = t2.x; f[2 * q + 1] = t2.y;
            }
            float s = 0.0f, s2 = 0.0f;
#pragma unroll
            for (int q = 0; q < 8; q++) { s += f[q]; s2 += f[q] * f[q]; }
#pragma unroll
            for (int o = 16; o; o >>= 1) {
                s  += __shfl_xor_sync(0xffffffffu, s, o);
                s2 += __shfl_xor_sync(0xffffffffu, s2, o);
            }
            float mu = s * (1.0f / HH);
            float rs = rsqrtf(s2 * (1.0f / HH) - mu * mu + 1e-5f);
#pragma unroll
            for (int q = 0; q < 8; q++) {
                int c = pos * 8 + q;
                f[q] = (f[q] - mu) * rs * __ldg(&gamma[c]) + __ldg(&beta[c]);
            }
#pragma unroll
            for (int q = 0; q < 4; q++)
                vp[q] = __floats2bfloat162_rn(f[2 * q], f[2 * q + 1]);
            *(uint4*)(smA + row * AST * 2 + pos * 16) = v;
        }
    } else {
        for (int u = tid; u < 64 * (KD / 8); u += 256) {
            int row = u / (KD / 8), pos = u % (KD / 8);
            uint4 v = *(const uint4*)(A + (m0 + row) * KD + pos * 8);
            *(uint4*)(smA + row * AST * 2 + pos * 16) = v;
        }
    }
    if (HEADS) {
        for (int u = tid; u < 1024; u += 256) {
            int row = u >> 5, q = u & 31;
            *(uint4*)(smW + row * 528 + q * 16) = *(const uint4*)(g_Whd + row * M2 + q * 8);
        }
    }

    uint4 breg[BLD];
#pragma unroll
    for (int i = 0; i < BLD; i++) {
        int u = tid + i * 256;
        int row = u >> 2, q = u & 3;
        breg[i] = *(const uint4*)(Bw + (size_t)(n0 + row) * KD + q * 8);
    }

    float acc[2][AN][4];
#pragma unroll
    for (int i = 0; i < 2; i++)
#pragma unroll
        for (int j = 0; j < AN; j++)
#pragma unroll
            for (int k = 0; k < 4; k++) acc[i][j][k] = 0.0f;

    const int mi = lane >> 3;
    const int rowoff = ((mi & 1) << 3) + (lane & 7);
    const uint32_t kb16 = (uint32_t)((mi >> 1) << 4);
    const uint32_t smAu = smem_u32(smA);
    const uint32_t smBu = smem_u32(smB);
    uint32_t aB[2], bB[P];
#pragma unroll
    for (int am = 0; am < 2; am++)
        aB[am] = smAu + (wm * 32 + am * 16 + rowoff) * (AST * 2) + kb16;
#pragma unroll
    for (int p = 0; p < P; p++)
        bB[p] = smBu + (wn * (NT / 4) + p * 16 + rowoff) * 80 + kb16;

#pragma unroll 1
    for (int c = 0; c < CH; c++) {
        __syncthreads();
#pragma unroll
        for (int i = 0; i < BLD; i++) {
            int u = tid + i * 256;
            int row = u >> 2, q = u & 3;
            *(uint4*)(smB + row * 80 + q * 16) = breg[i];
        }
        __syncthreads();
        if (c + 1 < CH) {
#pragma unroll
            for (int i = 0; i < BLD; i++) {
                int u = tid + i * 256;
                int row = u >> 2, q = u & 3;
                breg[i] = *(const uint4*)(Bw + (size_t)(n0 + row) * KD + (c + 1) * 32 + q * 8);
            }
        }
#pragma unroll
        for (int ks = 0; ks < 2; ks++) {
            int s = c * 2 + ks;
            uint32_t a[2][4];
            ldsm4(a[0][0], a[0][1], a[0][2], a[0][3], aB[0] + s * 32);
            ldsm4(a[1][0], a[1][1], a[1][2], a[1][3], aB[1] + s * 32);
#pragma unroll
            for (int p = 0; p < P; p++) {
                uint32_t br0, br1, br2, br3;
                ldsm4(br0, br1, br2, br3, bB[p] + ks * 32);
#pragma unroll
                for (int am = 0; am < 2; am++) {
                    mma16816(acc[am][2 * p],     a[am][0], a[am][1], a[am][2], a[am][3], br0, br2);
                    mma16816(acc[am][2 * p + 1], a[am][0], a[am][1], a[am][2], a[am][3], br1, br3);
                }
            }
        }
    }

    if (!HEADS) {
#pragma unroll
        for (int am = 0; am < 2; am++)
#pragma unroll
            for (int an = 0; an < AN; an++) {
                size_t r = m0 + wm * 32 + am * 16 + g8;
                int c = n0 + wn * (NT / 4) + an * 8 + t4 * 2;
                float bc0 = __ldg(&bias[c]), bc1 = __ldg(&bias[c + 1]);
                float v0 = acc[am][an][0] + bc0;
                float v1 = acc[am][an][1] + bc1;
                v0 = (v0 > 0.0f) ? v0 : expm1f(v0);
                v1 = (v1 > 0.0f) ? v1 : expm1f(v1);
                *(__nv_bfloat162*)(Out + r * (M1) + c) = __floats2bfloat162_rn(v0, v1);
                float v2 = acc[am][an][2] + bc0;
                float v3 = acc[am][an][3] + bc1;
                v2 = (v2 > 0.0f) ? v2 : expm1f(v2);
                v3 = (v3 > 0.0f) ? v3 : expm1f(v3);
                *(__nv_bfloat162*)(Out + (r + 8) * (M1) + c) = __floats2bfloat162_rn(v2, v3);
            }
    } else {
        // ---- tensor-core heads epilogue ----
        __syncthreads();
        char* ys = smA;
#pragma unroll
        for (int am = 0; am < 2; am++)
#pragma unroll
            for (int an = 0; an < AN; an++) {
                int r = wm * 32 + am * 16 + g8;
                int c = wn * (NT / 4) + an * 8 + t4 * 2;
                float bc0 = __ldg(&bias[c]), bc1 = __ldg(&bias[c + 1]);
                float v0 = acc[am][an][0] + bc0;
                float v1 = acc[am][an][1] + bc1;
                v0 = (v0 > 0.0f) ? v0 : expm1f(v0);
                v1 = (v1 > 0.0f) ? v1 : expm1f(v1);
                *(__nv_bfloat162*)(ys + r * 528 + c * 2) = __floats2bfloat162_rn(v0, v1);
                float v2 = acc[am][an][2] + bc0;
                float v3 = acc[am][an][3] + bc1;
                v2 = (v2 > 0.0f) ? v2 : expm1f(v2);
                v3 = (v3 > 0.0f) ? v3 : expm1f(v3);
                *(__nv_bfloat162*)(ys + (r + 8) * 528 + c * 2) = __floats2bfloat162_rn(v2, v3);
            }
        __syncthreads();

        if (warp < 4) {
            const uint32_t aH = smem_u32(ys) + (warp * 16 + rowoff) * 528 + kb16;
            const uint32_t smWu = smem_u32(smW);
            const uint32_t bH0 = smWu + rowoff * 528 + kb16;
            const uint32_t bH1 = smWu + (16 + rowoff) * 528 + kb16;

            float ah[4][4];
#pragma unroll
            for (int i = 0; i < 4; i++)
#pragma unroll
                for (int k = 0; k < 4; k++) ah[i][k] = 0.0f;

#pragma unroll
            for (int s = 0; s < 16; s++) {
                uint32_t a0, a1, a2, a3;
                ldsm4(a0, a1, a2, a3, aH + s * 32);
                uint32_t b0, b1, b2, b3;
                ldsm4(b0, b1, b2, b3, bH0 + s * 32);
                mma16816(ah[0], a0, a1, a2, a3, b0, b2);
                mma16816(ah[1], a0, a1, a2, a3, b1, b3);
                ldsm4(b0, b1, b2, b3, bH1 + s * 32);
                mma16816(ah[2], a0, a1, a2, a3, b0, b2);
                mma16816(ah[3], a0, a1, a2, a3, b1, b3);
            }

            int r = warp * 16 + g8;
            float Slo = 0.0f, Shi = 0.0f;
#pragma unroll
            for (int an = 0; an < 4; an++)
#pragma unroll
                for (int j = 0; j < 2; j++) {
                    int o = an * 8 + t4 * 2 + j;
                    float vlo = ah[an][j], vhi = ah[an][2 + j];
                    if (o < 12) {
                        float bb = __ldg(&bm[o]);
                        outF[(m0 + r) * 14 + o]     = vlo + bb;
                        outF[(m0 + r + 8) * 14 + o] = vhi + bb;
                    } else if (o < 24) {
                        float bb = __ldg(&bsv[o - 12]);
                        Slo += fminf(fmaxf(vlo + bb, -5.0f), 2.0f);
                        Shi += fminf(fmaxf(vhi + bb, -5.0f), 2.0f);
                    }
                }
            Slo += __shfl_xor_sync(0xffffffffu, Slo, 1);
            Slo += __shfl_xor_sync(0xffffffffu, Slo, 2);
            Shi += __shfl_xor_sync(0xffffffffu, Shi, 1);
            Shi += __shfl_xor_sync(0xffffffffu, Shi, 2);
            if (t4 == 0) {
                outF[(m0 + r) * 14 + 12]     = -Slo - 6.0f * LOG2PI;
                outF[(m0 + r) * 14 + 13]     = Slo + 6.0f + 6.0f * LOG2PI;
                outF[(m0 + r + 8) * 14 + 12] = -Shi - 6.0f * LOG2PI;
                outF[(m0 + r + 8) * 14 + 13] = Shi + 6.0f + 6.0f * LOG2PI;
            }
        }
    }
}

// ---------------- launch ----------------
extern "C" void kernel_launch(void* const* d_in, const int* in_sizes, int n_in,
                              void* d_out, int out_size)
{
    const float *x, *h0, *c0, *W_ih, *W_hh, *b_ih, *b_hh, *ln_g, *ln_b;
    const float *W1, *b1, *W2, *b2, *Wm, *bm, *Ws, *bs;
    const int* done;

    if (in_sizes[1] == TT * BB) {
        // setup_inputs dict order
        x = (const float*)d_in[0];  done = (const int*)d_in[1];
        h0 = (const float*)d_in[2]; c0 = (const float*)d_in[3];
        W_ih = (const float*)d_in[4]; W_hh = (const float*)d_in[5];
        b_ih = (const float*)d_in[6]; b_hh = (const float*)d_in[7];
        ln_g = (const float*)d_in[8]; ln_b = (const float*)d_in[9];
        W1 = (const float*)d_in[10]; b1 = (const float*)d_in[11];
        W2 = (const float*)d_in[12]; b2 = (const float*)d_in[13];
        Wm = (const float*)d_in[14]; bm = (const float*)d_in[15];
        Ws = (const float*)d_in[16]; bs = (const float*)d_in[17];
    } else {
        // reference() signature order
        x = (const float*)d_in[0];
        h0 = (const float*)d_in[1]; c0 = (const float*)d_in[2];
        W_ih = (const float*)d_in[3]; W_hh = (const float*)d_in[4];
        b_ih = (const float*)d_in[5]; b_hh = (const float*)d_in[6];
        ln_g = (const float*)d_in[7]; ln_b = (const float*)d_in[8];
        W1 = (const float*)d_in[9];  b1 = (const float*)d_in[10];
        W2 = (const float*)d_in[11]; b2 = (const float*)d_in[12];
        Wm = (const float*)d_in[13]; bm = (const float*)d_in[14];
        Ws = (const float*)d_in[15]; bs = (const float*)d_in[16];
        done = (const int*)d_in[17];
    }

    float* out = (float*)d_out;

    bf16 *p_hb, *p_W1b, *p_W2b, *p_y1;
    cudaGetSymbolAddress((void**)&p_hb, g_hb);
    cudaGetSymbolAddress((void**)&p_W1b, g_W1b);
    cudaGetSymbolAddress((void**)&p_W2b, g_W2b);
    cudaGetSymbolAddress((void**)&p_y1, g_y1);

    const int SM1 = 64 * (HH + 8) * 2 + 128 * 80;                 // 44032
    const int SM2 = 64 * (M1 + 8) * 2 + 256 * 80 + 32 * 528;      // 103936

    cudaFuncSetAttribute(lstm_persist, cudaFuncAttributeMaxDynamicSharedMemorySize, SM_TOTAL);
    cudaFuncSetAttribute(gemm_hot<HH, 128, true, false>,
                         cudaFuncAttributeMaxDynamicSharedMemorySize, SM1);
    cudaFuncSetAttribute(gemm_hot<M1, 256, false, true>,
                         cudaFuncAttributeMaxDynamicSharedMemorySize, SM2);

    // 0. single merged prep
    prep_all<<<(PREP_TOTAL + 255) / 256, 256>>>(x, W_hh, W_ih, b_ih, b_hh,
                                                W1, W2, Wm, Ws);

    // 1. persistent cluster LSTM
    lstm_persist<<<128, 256, SM_TOTAL>>>(h0, c0, done);

    // 2. MLP1 (LN fused in-kernel)
    gemm_hot<HH, 128, true, false><<<dim3(TB / 64, M1 / 128), 256, SM1>>>(
        p_hb, p_W1b, b1, p_y1, ln_g, ln_b, nullptr, nullptr, nullptr);

    // 3. MLP2 + tensor-core heads
    gemm_hot<M1, 256, false, true><<<dim3(TB / 64, 1), 256, SM2>>>(
        p_y1, p_W2b, b2, nullptr, nullptr, nullptr, bm, bs, out);
}

// round 14
// speedup vs baseline: 1.3179x; 1.0235x over previous
#include <cuda_runtime.h>
#include <cuda_bf16.h>
#include <math.h>
#include <stdint.h>

#define TT 64
#define BB 2048
#define OBS 48
#define HH 256
#define G4 1024
#define KC 304
#define M1 512
#define M2 256
#define TB (TT*BB)
#define LOG2PI 1.8378770664093453f

typedef __nv_bfloat16 bf16;

// ---------------- scratch ----------------
__device__ __align__(16) bf16 g_Wc[G4 * KC];
__device__ float            g_bias[G4];
__device__ __align__(16) bf16 g_W1b[M1 * HH];
__device__ __align__(16) bf16 g_W2b[M2 * M1];
__device__ __align__(16) bf16 g_Whd[32 * M2];        // [Wm|Ws|0] head weights, [o][k]
__device__ __align__(16) bf16 g_xb[(size_t)TB * OBS];
__device__ __align__(16) bf16 g_hb[(size_t)TB * HH];
__device__ __align__(16) bf16 g_y1[(size_t)TB * M1];

// ---------------- helpers ----------------
__device__ __forceinline__ uint32_t bf2_as_u32(__nv_bfloat162 v) {
    return *reinterpret_cast<uint32_t*>(&v);
}

__device__ __forceinline__ void mma16816(float c[4],
    uint32_t a0, uint32_t a1, uint32_t a2, uint32_t a3,
    uint32_t b0, uint32_t b1)
{
    asm volatile(
        "mma.sync.aligned.m16n8k16.row.col.f32.bf16.bf16.f32 "
        "{%0,%1,%2,%3}, {%4,%5,%6,%7}, {%8,%9}, {%0,%1,%2,%3};"
        : "+f"(c[0]), "+f"(c[1]), "+f"(c[2]), "+f"(c[3])
        : "r"(a0), "r"(a1), "r"(a2), "r"(a3), "r"(b0), "r"(b1));
}

__device__ __forceinline__ void ldsm4(uint32_t& r0, uint32_t& r1,
                                      uint32_t& r2, uint32_t& r3, uint32_t addr)
{
    asm volatile("ldmatrix.sync.aligned.m8n8.x4.shared.b16 {%0,%1,%2,%3}, [%4];"
                 : "=r"(r0), "=r"(r1), "=r"(r2), "=r"(r3) : "r"(addr));
}

__device__ __forceinline__ uint32_t smem_u32(const void* p) {
    uint32_t a;
    asm("{ .reg .u64 t; cvta.to.shared.u64 t, %1; cvt.u32.u64 %0, t; }"
        : "=r"(a) : "l"(p));
    return a;
}

__device__ __forceinline__ float tanha(float x) {
    float r; asm("tanh.approx.f32 %0, %1;" : "=f"(r) : "f"(x)); return r;
}
__device__ __forceinline__ float sigm(float x) {
    return fmaf(0.5f, tanha(0.5f * x), 0.5f);
}

// ---------------- merged prep kernel ----------------
#define XSEG   ((TB * OBS) / 4)
#define WCSEG  (G4 * KC)
#define W12SEG (M1 * HH + M2 * M1)
#define WHDSEG (32 * M2)
#define PREP_TOTAL (XSEG + WCSEG + W12SEG + WHDSEG)

__global__ void prep_all(
    const float* __restrict__ x,
    const float* __restrict__ W_hh, const float* __restrict__ W_ih,
    const float* __restrict__ b_ih, const float* __restrict__ b_hh,
    const float* __restrict__ W1, const float* __restrict__ W2,
    const float* __restrict__ Wm, const float* __restrict__ Ws)
{
    int idx = blockIdx.x * blockDim.x + threadIdx.x;
    if (idx < XSEG) {
        float4 v = *(const float4*)(x + (size_t)idx * 4);
        uint2 p;
        p.x = bf2_as_u32(__floats2bfloat162_rn(v.x, v.y));
        p.y = bf2_as_u32(__floats2bfloat162_rn(v.z, v.w));
        *(uint2*)(g_xb + (size_t)idx * 4) = p;
        return;
    }
    idx -= XSEG;
    if (idx < WCSEG) {
        int n = idx / KC, k = idx % KC;
        int g = n & 3, j = n >> 2;
        float v = (k < HH) ? W_hh[(size_t)(g * HH + j) * HH + k]
                           : W_ih[(size_t)(g * HH + j) * OBS + (k - HH)];
        g_Wc[idx] = __float2bfloat16(v);
        if (k == 0) g_bias[n] = b_ih[g * HH + j] + b_hh[g * HH + j];
        return;
    }
    idx -= WCSEG;
    if (idx < W12SEG) {
        if (idx < M1 * HH) {
            int n = idx / HH, k = idx % HH;
            g_W1b[idx] = __float2bfloat16(W1[(size_t)k * M1 + n]);
        } else {
            int i = idx - M1 * HH;
            int n = i / M1, k = i % M1;
            g_W2b[i] = __float2bfloat16(W2[(size_t)k * M2 + n]);
        }
        return;
    }
    idx -= W12SEG;
    if (idx < WHDSEG) {
        int o = idx / M2, k = idx % M2;
        float v = 0.0f;
        if (o < 12) v = Wm[k * 12 + o];
        else if (o < 24) v = Ws[k * 12 + (o - 12)];
        g_Whd[idx] = __float2bfloat16(v);
    }
}

// ---------------- persistent cluster LSTM (proven; unchanged) ----------------
#define SM_BIAS  0
#define SM_A     1024
#define SM_STAGE 43008
#define SM_B     52224
#define SM_TOTAL 220160
#define ASTR_B 656
#define STG_B  144

__global__ void __launch_bounds__(256, 1) __cluster_dims__(4, 1, 1)
lstm_persist(const float* __restrict__ h0, const float* __restrict__ c0,
             const int* __restrict__ done)
{
    extern __shared__ char smx[];
    const uint32_t smb = smem_u32(smx);

    const int tid = threadIdx.x;
    const int lane = tid & 31, warp = tid >> 5;
    const int wm = warp & 1, wn = warp >> 1;
    const int g8 = lane >> 2, t4 = lane & 3;

    uint32_t rank;
    asm("mov.u32 %0, %%cluster_ctarank;" : "=r"(rank));
    const int b0 = (blockIdx.x >> 2) * 64;
    const int jbase = rank * 64;

    float* bias_s = (float*)(smx + SM_BIAS);
    bias_s[tid] = g_bias[rank * 256 + tid];

    for (int u = tid; u < 256 * 38; u += 256) {
        int n = u / 38, off = u % 38;
        uint4 v = *(const uint4*)((const char*)g_Wc + (size_t)(rank * 256 + n) * 608 + off * 16);
        *(uint4*)(smx + SM_B + n * ASTR_B + off * 16) = v;
    }
    for (int u = tid; u < 4096; u += 256) {
        int row = u >> 6, c4 = u & 63;
        float4 v = *(const float4*)(h0 + (size_t)(b0 + row) * HH + c4 * 4);
        uint2 p;
        p.x = bf2_as_u32(__floats2bfloat162_rn(v.x, v.y));
        p.y = bf2_as_u32(__floats2bfloat162_rn(v.z, v.w));
        *(uint2*)(smx + SM_A + row * ASTR_B + c4 * 8) = p;
    }
    {
        const uint4* xs = (const uint4*)(g_xb + (size_t)b0 * OBS);
        for (int u = tid; u < 384; u += 256) {
            uint4 v = xs[u];
            int e = u * 8, row = e / 48, col = e % 48;
            *(uint4*)(smx + SM_A + row * ASTR_B + 512 + col * 2) = v;
        }
    }
    float creg[16];
#pragma unroll
    for (int am = 0; am < 2; am++)
#pragma unroll
        for (int an = 0; an < 8; an++) {
            int r = wm * 32 + am * 16 + g8 + (t4 & 1) * 8;
            int jl = wn * 16 + an * 2 + (t4 >> 1);
            creg[am * 8 + an] = c0[(size_t)(b0 + r) * HH + jbase + jl];
        }
    __syncthreads();

    const int mi = lane >> 3;
    const int rowoff = ((mi & 1) << 3) + (lane & 7);
    const uint32_t kboff = (uint32_t)((mi >> 1) << 4);
    uint32_t aBase[2], bBase[4];
#pragma unroll
    for (int am = 0; am < 2; am++)
        aBase[am] = smb + SM_A + (wm * 32 + am * 16 + rowoff) * ASTR_B + kboff;
#pragma unroll
    for (int p = 0; p < 4; p++)
        bBase[p] = smb + SM_B + (wn * 64 + p * 16 + rowoff) * ASTR_B + kboff;

    uint32_t peerA[4];
#pragma unroll
    for (int r = 0; r < 4; r++) {
        uint32_t a;
        asm("mapa.shared::cluster.u32 %0, %1, %2;" : "=r"(a) : "r"(smb + SM_A), "r"(r));
        peerA[r] = a;
    }

    const int base_r = wm * 32 + g8;
    int d0, d1, d2, d3;
    {
        const int* dt = done + b0;
        d0 = dt[base_r]; d1 = dt[base_r + 8];
        d2 = dt[base_r + 16]; d3 = dt[base_r + 24];
    }

#pragma unroll 1
    for (int t = 0; t < TT; t++) {
        uint32_t m0 = d0 ? 0u : ~0u, m1 = d1 ? 0u : ~0u;
        uint32_t m2 = d2 ? 0u : ~0u, m3 = d3 ? 0u : ~0u;

        float acc[2][8][4];
#pragma unroll
        for (int i = 0; i < 2; i++)
#pragma unroll
            for (int j = 0; j < 8; j++)
#pragma unroll
                for (int k = 0; k < 4; k++) acc[i][j][k] = 0.0f;

        if (t)
            asm volatile("barrier.cluster.wait.aligned;" ::: "memory");

#pragma unroll
        for (int ch = 0; ch < 19; ch++) {
            uint32_t a[2][4];
            ldsm4(a[0][0], a[0][1], a[0][2], a[0][3], aBase[0] + ch * 32);
            ldsm4(a[1][0], a[1][1], a[1][2], a[1][3], aBase[1] + ch * 32);
            if (ch < 16) {
                a[0][0] &= m0; a[0][2] &= m0; a[0][1] &= m1; a[0][3] &= m1;
                a[1][0] &= m2; a[1][2] &= m2; a[1][1] &= m3; a[1][3] &= m3;
            }
#pragma unroll
            for (int p = 0; p < 4; p++) {
                uint32_t br0, br1, br2, br3;
                ldsm4(br0, br1, br2, br3, bBase[p] + ch * 32);
#pragma unroll
                for (int am = 0; am < 2; am++) {
                    mma16816(acc[am][2 * p],     a[am][0], a[am][1], a[am][2], a[am][3], br0, br2);
                    mma16816(acc[am][2 * p + 1], a[am][0], a[am][1], a[am][2], a[am][3], br1, br3);
                }
            }
        }

        asm volatile("barrier.cluster.arrive.aligned;" ::: "memory");   // B1 arrive

        uint4 xr0, xr1;
        int dn0 = 0, dn1 = 0, dn2 = 0, dn3 = 0;
        const bool hx = (t < TT - 1);
        if (hx) {
            const uint4* xs = (const uint4*)(g_xb + ((size_t)(t + 1) * BB + b0) * OBS);
            xr0 = xs[tid];
            if (tid < 128) xr1 = xs[tid + 256];
            const int* dt = done + (size_t)(t + 1) * BB + b0;
            dn0 = dt[base_r]; dn1 = dt[base_r + 8];
            dn2 = dt[base_r + 16]; dn3 = dt[base_r + 24];
        }

        const bool odd = (t4 & 1);
#pragma unroll
        for (int am = 0; am < 2; am++) {
            const int dlo = (am == 0) ? d0 : d2;
            const int dhi = (am == 0) ? d1 : d3;
            const int dflag = odd ? dhi : dlo;
#pragma unroll
            for (int an = 0; an < 8; an++) {
                float* a = acc[am][an];
                float s0 = odd ? a[0] : a[2];
                float s1 = odd ? a[1] : a[3];
                float e0 = __shfl_xor_sync(0xffffffffu, s0, 1);
                float e1 = __shfl_xor_sync(0xffffffffu, s1, 1);
                float q0 = odd ? e0 : a[0];
                float q1 = odd ? e1 : a[1];
                float q2 = odd ? a[2] : e0;
                float q3 = odd ? a[3] : e1;
                int jl = wn * 16 + an * 2 + (t4 >> 1);
                float4 bb = *(const float4*)&bias_s[jl * 4];
                float gi = q0 + bb.x, gf = q1 + bb.y, gg = q2 + bb.z, go = q3 + bb.w;
                int cell = am * 8 + an;
                float cold = dflag ? 0.0f : creg[cell];
                float cn = sigm(gf) * cold + sigm(gi) * tanha(gg);
                creg[cell] = cn;
                float hn = sigm(go) * tanha(cn);
                int r = wm * 32 + am * 16 + g8 + (odd ? 8 : 0);
                *(bf16*)(smx + SM_STAGE + r * STG_B + jl * 2) = __float2bfloat16(hn);
            }
        }

        if (hx) {
            int e = tid * 8;
            *(uint4*)(smx + SM_A + (e / 48) * ASTR_B + 512 + (e % 48) * 2) = xr0;
            if (tid < 128) {
                int e2 = (tid + 256) * 8;
                *(uint4*)(smx + SM_A + (e2 / 48) * ASTR_B + 512 + (e2 % 48) * 2) = xr1;
            }
        }

        __syncthreads();
        asm volatile("barrier.cluster.wait.aligned;" ::: "memory");     // B1 wait

#pragma unroll
        for (int q = 0; q < 2; q++) {
            int u = tid + q * 256;
            int row = u >> 3, off = u & 7;
            uint4 v = *(const uint4*)(smx + SM_STAGE + row * STG_B + off * 16);
#pragma unroll
            for (int r = 0; r < 4; r++) {
                uint32_t da = peerA[r] + row * ASTR_B + jbase * 2 + off * 16;
                asm volatile("st.shared::cluster.v4.b32 [%0], {%1,%2,%3,%4};"
                             :: "r"(da), "r"(v.x), "r"(v.y), "r"(v.z), "r"(v.w) : "memory");
            }
            *(uint4*)(g_hb + ((size_t)t * BB + b0 + row) * HH + jbase + off * 8) = v;
        }

        asm volatile("barrier.cluster.arrive.aligned;" ::: "memory");   // B2 arrive
        d0 = dn0; d1 = dn1; d2 = dn2; d3 = dn3;
    }
    asm volatile("barrier.cluster.wait.aligned;" ::: "memory");
}

// ---------------- A-hot GEMM; double-buffered B, one sync per chunk ----------------
template <int KD, int NT, bool LNA, bool HEADS>
__global__ __launch_bounds__(256) void gemm_hot(
    const bf16* __restrict__ A, const bf16* __restrict__ Bw,
    const float* __restrict__ bias, bf16* __restrict__ Out,
    const float* __restrict__ gamma, const float* __restrict__ beta,
    const float* __restrict__ bm, const float* __restrict__ bsv,
    float* __restrict__ outF)
{
    constexpr int AST = KD + 8;
    constexpr int ASZ = 64 * AST * 2;
    constexpr int P   = NT / 64;
    constexpr int AN  = NT / 32;
    constexpr int CH  = KD / 32;
    constexpr int BLD = NT / 64;
    constexpr int BUFB = NT * 80;            // one B buffer (32-K chunk)

    extern __shared__ char sm[];
    char* smA  = sm;
    char* smB0 = sm + ASZ;                   // ping
    char* smB1 = sm + ASZ + BUFB;            // pong
    char* smW  = smB0;                       // HEADS: reuse B region post-loop

    const int tid = threadIdx.x;
    const int lane = tid & 31, warp = tid >> 5;
    const int wm = warp & 1, wn = warp >> 1;
    const int g8 = lane >> 2, t4 = lane & 3;
    const size_t m0 = (size_t)blockIdx.x * 64;
    const int n0 = blockIdx.y * NT;

    // ---- load A tile (once); LN in-kernel if LNA ----
    if (LNA) {
#pragma unroll
        for (int it = 0; it < 64 * (KD / 8) / 256; it++) {
            int u = tid + it * 256;
            int row = u >> 5, pos = u & 31;
            uint4 v = *(const uint4*)(A + (m0 + row) * KD + pos * 8);
            __nv_bfloat162* vp = (__nv_bfloat162*)&v;
            float f[8];
#pragma unroll
            for (int q = 0; q < 4; q++) {
                float2 t2 = __bfloat1622float2(vp[q]);
                f[2 * q] = t2.x; f[2 * q + 1] = t2.y;
            }
            float s = 0.0f, s2 = 0.0f;
#pragma unroll
            for (int q = 0; q < 8; q++) { s += f[q]; s2 += f[q] * f[q]; }
#pragma unroll
            for (int o = 16; o; o >>= 1) {
                s  += __shfl_xor_sync(0xffffffffu, s, o);
                s2 += __shfl_xor_sync(0xffffffffu, s2, o);
            }
            float mu = s * (1.0f / HH);
            float rs = rsqrtf(s2 * (1.0f / HH) - mu * mu + 1e-5f);
#pragma unroll
            for (int q = 0; q < 8; q++) {
                int c = pos * 8 + q;
                f[q] = (f[q] - mu) * rs * __ldg(&gamma[c]) + __ldg(&beta[c]);
            }
#pragma unroll
            for (int q = 0; q < 4; q++)
                vp[q] = __floats2bfloat162_rn(f[2 * q], f[2 * q + 1]);
            *(uint4*)(smA + row * AST * 2 + pos * 16) = v;
        }
    } else {
        for (int u = tid; u < 64 * (KD / 8); u += 256) {
            int row = u / (KD / 8), pos = u % (KD / 8);
            uint4 v = *(const uint4*)(A + (m0 + row) * KD + pos * 8);
            *(uint4*)(smA + row * AST * 2 + pos * 16) = v;
        }
    }

    uint4 breg[BLD];
#pragma unroll
    for (int i = 0; i < BLD; i++) {
        int u = tid + i * 256;
        int row = u >> 2, q = u & 3;
        breg[i] = *(const uint4*)(Bw + (size_t)(n0 + row) * KD + q * 8);
    }

    float acc[2][AN][4];
#pragma unroll
    for (int i = 0; i < 2; i++)
#pragma unroll
        for (int j = 0; j < AN; j++)
#pragma unroll
            for (int k = 0; k < 4; k++) acc[i][j][k] = 0.0f;

    const int mi = lane >> 3;
    const int rowoff = ((mi & 1) << 3) + (lane & 7);
    const uint32_t kb16 = (uint32_t)((mi >> 1) << 4);
    const uint32_t smAu = smem_u32(smA);
    const uint32_t smB0u = smem_u32(smB0);
    uint32_t aB[2], bB[P];
#pragma unroll
    for (int am = 0; am < 2; am++)
        aB[am] = smAu + (wm * 32 + am * 16 + rowoff) * (AST * 2) + kb16;
#pragma unroll
    for (int p = 0; p < P; p++)
        bB[p] = smB0u + (wn * (NT / 4) + p * 16 + rowoff) * 80 + kb16;

    // store offset within buffer for this thread's B transfers
    const int bsrow = tid >> 2, bsq = tid & 3;

    // ---- K loop: one __syncthreads per chunk (double-buffered B) ----
#pragma unroll 1
    for (int c = 0; c < CH; c++) {
        const uint32_t bufOff = (c & 1) ? (uint32_t)BUFB : 0u;
        char* bufc = (c & 1) ? smB1 : smB0;
#pragma unroll
        for (int i = 0; i < BLD; i++) {
            int row = bsrow + i * 64;
            *(uint4*)(bufc + row * 80 + bsq * 16) = breg[i];
        }
        __syncthreads();
        if (c + 1 < CH) {
#pragma unroll
            for (int i = 0; i < BLD; i++) {
                int row = bsrow + i * 64;
                breg[i] = *(const uint4*)(Bw + (size_t)(n0 + row) * KD + (c + 1) * 32 + bsq * 8);
            }
        }
#pragma unroll
        for (int ks = 0; ks < 2; ks++) {
            int s = c * 2 + ks;
            uint32_t a[2][4];
            ldsm4(a[0][0], a[0][1], a[0][2], a[0][3], aB[0] + s * 32);
            ldsm4(a[1][0], a[1][1], a[1][2], a[1][3], aB[1] + s * 32);
#pragma unroll
            for (int p = 0; p < P; p++) {
                uint32_t br0, br1, br2, br3;
                ldsm4(br0, br1, br2, br3, bB[p] + bufOff + ks * 32);
#pragma unroll
                for (int am = 0; am < 2; am++) {
                    mma16816(acc[am][2 * p],     a[am][0], a[am][1], a[am][2], a[am][3], br0, br2);
                    mma16816(acc[am][2 * p + 1], a[am][0], a[am][1], a[am][2], a[am][3], br1, br3);
                }
            }
        }
    }

    if (!HEADS) {
#pragma unroll
        for (int am = 0; am < 2; am++)
#pragma unroll
            for (int an = 0; an < AN; an++) {
                size_t r = m0 + wm * 32 + am * 16 + g8;
                int c = n0 + wn * (NT / 4) + an * 8 + t4 * 2;
                float bc0 = __ldg(&bias[c]), bc1 = __ldg(&bias[c + 1]);
                float v0 = acc[am][an][0] + bc0;
                float v1 = acc[am][an][1] + bc1;
                v0 = (v0 > 0.0f) ? v0 : expm1f(v0);
                v1 = (v1 > 0.0f) ? v1 : expm1f(v1);
                *(__nv_bfloat162*)(Out + r * (M1) + c) = __floats2bfloat162_rn(v0, v1);
                float v2 = acc[am][an][2] + bc0;
                float v3 = acc[am][an][3] + bc1;
                v2 = (v2 > 0.0f) ? v2 : expm1f(v2);
                v3 = (v3 > 0.0f) ? v3 : expm1f(v3);
                *(__nv_bfloat162*)(Out + (r + 8) * (M1) + c) = __floats2bfloat162_rn(v2, v3);
            }
    } else {
        // ---- tensor-core heads epilogue ----
        __syncthreads();                     // K-loop reads of smA/smB done
        // y2 (ELU, bf16) -> ys aliasing smA; head weights -> smW (reusing B buf)
        char* ys = smA;
        for (int u = tid; u < 1024; u += 256) {
            int row = u >> 5, q = u & 31;
            *(uint4*)(smW + row * 528 + q * 16) = *(const uint4*)(g_Whd + row * M2 + q * 8);
        }
#pragma unroll
        for (int am = 0; am < 2; am++)
#pragma unroll
            for (int an = 0; an < AN; an++) {
                int r = wm * 32 + am * 16 + g8;
                int c = wn * (NT / 4) + an * 8 + t4 * 2;
                float bc0 = __ldg(&bias[c]), bc1 = __ldg(&bias[c + 1]);
                float v0 = acc[am][an][0] + bc0;
                float v1 = acc[am][an][1] + bc1;
                v0 = (v0 > 0.0f) ? v0 : expm1f(v0);
                v1 = (v1 > 0.0f) ? v1 : expm1f(v1);
                *(__nv_bfloat162*)(ys + r * 528 + c * 2) = __floats2bfloat162_rn(v0, v1);
                float v2 = acc[am][an][2] + bc0;
                float v3 = acc[am][an][3] + bc1;
                v2 = (v2 > 0.0f) ? v2 : expm1f(v2);
                v3 = (v3 > 0.0f) ? v3 : expm1f(v3);
                *(__nv_bfloat162*)(ys + (r + 8) * 528 + c * 2) = __floats2bfloat162_rn(v2, v3);
            }
        __syncthreads();

        if (warp < 4) {
            const uint32_t aH = smem_u32(ys) + (warp * 16 + rowoff) * 528 + kb16;
            const uint32_t smWu = smem_u32(smW);
            const uint32_t bH0 = smWu + rowoff * 528 + kb16;
            const uint32_t bH1 = smWu + (16 + rowoff) * 528 + kb16;

            float ah[4][4];
#pragma unroll
            for (int i = 0; i < 4; i++)
#pragma unroll
                for (int k = 0; k < 4; k++) ah[i][k] = 0.0f;

#pragma unroll
            for (int s = 0; s < 16; s++) {
                uint32_t a0, a1, a2, a3;
                ldsm4(a0, a1, a2, a3, aH + s * 32);
                uint32_t b0, b1, b2, b3;
                ldsm4(b0, b1, b2, b3, bH0 + s * 32);
                mma16816(ah[0], a0, a1, a2, a3, b0, b2);
                mma16816(ah[1], a0, a1, a2, a3, b1, b3);
                ldsm4(b0, b1, b2, b3, bH1 + s * 32);
                mma16816(ah[2], a0, a1, a2, a3, b0, b2);
                mma16816(ah[3], a0, a1, a2, a3, b1, b3);
            }

            int r = warp * 16 + g8;
            float Slo = 0.0f, Shi = 0.0f;
#pragma unroll
            for (int an = 0; an < 4; an++)
#pragma unroll
                for (int j = 0; j < 2; j++) {
                    int o = an * 8 + t4 * 2 + j;
                    float vlo = ah[an][j], vhi = ah[an][2 + j];
                    if (o < 12) {
                        float bb = __ldg(&bm[o]);
                        outF[(m0 + r) * 14 + o]     = vlo + bb;
                        outF[(m0 + r + 8) * 14 + o] = vhi + bb;
                    } else if (o < 24) {
                        float bb = __ldg(&bsv[o - 12]);
                        Slo += fminf(fmaxf(vlo + bb, -5.0f), 2.0f);
                        Shi += fminf(fmaxf(vhi + bb, -5.0f), 2.0f);
                    }
                }
            Slo += __shfl_xor_sync(0xffffffffu, Slo, 1);
            Slo += __shfl_xor_sync(0xffffffffu, Slo, 2);
            Shi += __shfl_xor_sync(0xffffffffu, Shi, 1);
            Shi += __shfl_xor_sync(0xffffffffu, Shi, 2);
            if (t4 == 0) {
                outF[(m0 + r) * 14 + 12]     = -Slo - 6.0f * LOG2PI;
                outF[(m0 + r) * 14 + 13]     = Slo + 6.0f + 6.0f * LOG2PI;
                outF[(m0 + r + 8) * 14 + 12] = -Shi - 6.0f * LOG2PI;
                outF[(m0 + r + 8) * 14 + 13] = Shi + 6.0f + 6.0f * LOG2PI;
            }
        }
    }
}

// ---------------- launch ----------------
extern "C" void kernel_launch(void* const* d_in, const int* in_sizes, int n_in,
                              void* d_out, int out_size)
{
    const float *x, *h0, *c0, *W_ih, *W_hh, *b_ih, *b_hh, *ln_g, *ln_b;
    const float *W1, *b1, *W2, *b2, *Wm, *bm, *Ws, *bs;
    const int* done;

    if (in_sizes[1] == TT * BB) {
        // setup_inputs dict order
        x = (const float*)d_in[0];  done = (const int*)d_in[1];
        h0 = (const float*)d_in[2]; c0 = (const float*)d_in[3];
        W_ih = (const float*)d_in[4]; W_hh = (const float*)d_in[5];
        b_ih = (const float*)d_in[6]; b_hh = (const float*)d_in[7];
        ln_g = (const float*)d_in[8]; ln_b = (const float*)d_in[9];
        W1 = (const float*)d_in[10]; b1 = (const float*)d_in[11];
        W2 = (const float*)d_in[12]; b2 = (const float*)d_in[13];
        Wm = (const float*)d_in[14]; bm = (const float*)d_in[15];
        Ws = (const float*)d_in[16]; bs = (const float*)d_in[17];
    } else {
        // reference() signature order
        x = (const float*)d_in[0];
        h0 = (const float*)d_in[1]; c0 = (const float*)d_in[2];
        W_ih = (const float*)d_in[3]; W_hh = (const float*)d_in[4];
        b_ih = (const float*)d_in[5]; b_hh = (const float*)d_in[6];
        ln_g = (const float*)d_in[7]; ln_b = (const float*)d_in[8];
        W1 = (const float*)d_in[9];  b1 = (const float*)d_in[10];
        W2 = (const float*)d_in[11]; b2 = (const float*)d_in[12];
        Wm = (const float*)d_in[13]; bm = (const float*)d_in[14];
        Ws = (const float*)d_in[15]; bs = (const float*)d_in[16];
        done = (const int*)d_in[17];
    }

    float* out = (float*)d_out;

    bf16 *p_hb, *p_W1b, *p_W2b, *p_y1;
    cudaGetSymbolAddress((void**)&p_hb, g_hb);
    cudaGetSymbolAddress((void**)&p_W1b, g_W1b);
    cudaGetSymbolAddress((void**)&p_W2b, g_W2b);
    cudaGetSymbolAddress((void**)&p_y1, g_y1);

    const int SM1 = 64 * (HH + 8) * 2 + 2 * 128 * 80;            // 54272
    const int SM2 = 64 * (M1 + 8) * 2 + 2 * 256 * 80;            // 107520

    cudaFuncSetAttribute(lstm_persist, cudaFuncAttributeMaxDynamicSharedMemorySize, SM_TOTAL);
    cudaFuncSetAttribute(gemm_hot<HH, 128, true, false>,
                         cudaFuncAttributeMaxDynamicSharedMemorySize, SM1);
    cudaFuncSetAttribute(gemm_hot<M1, 256, false, true>,
                         cudaFuncAttributeMaxDynamicSharedMemorySize, SM2);

    // 0. single merged prep
    prep_all<<<(PREP_TOTAL + 255) / 256, 256>>>(x, W_hh, W_ih, b_ih, b_hh,
                                                W1, W2, Wm, Ws);

    // 1. persistent cluster LSTM
    lstm_persist<<<128, 256, SM_TOTAL>>>(h0, c0, done);

    // 2. MLP1 (LN fused in-kernel)
    gemm_hot<HH, 128, true, false><<<dim3(TB / 64, M1 / 128), 256, SM1>>>(
        p_hb, p_W1b, b1, p_y1, ln_g, ln_b, nullptr, nullptr, nullptr);

    // 3. MLP2 + tensor-core heads
    gemm_hot<M1, 256, false, true><<<dim3(TB / 64, 1), 256, SM2>>>(
        p_y1, p_W2b, b2, nullptr, nullptr, nullptr, bm, bs, out);
}